// round 1
// baseline (speedup 1.0000x reference)
#include <cuda_runtime.h>

// Problem constants
#define Bsz 4
#define Cch 512
#define Np  4096     // H*W = 64*64
#define Cqd 64

// Scratch (device globals; allocation-free per harness rules)
__device__ float g_q[Bsz * Np * Cqd];                       // [B][N][Cq]   4 MB
__device__ float g_k[Bsz * Np * Cqd];                       // [B][N][Cq]   4 MB
__device__ float g_v[Bsz * Np * Cch];                       // [B][N][C]   32 MB
__device__ float g_s[(size_t)Bsz * Np * Np];                // [B][N][N]  256 MB

// ---------------------------------------------------------------------------
// Projection: out[b][n][o] = sum_c W[o][c] * x[b][c][n] + bias[o]
// Tile: 128 n x 64 o, K-chunk 32. 256 threads, 8x4 microtile.
// ---------------------------------------------------------------------------
__global__ void proj_kernel(const float* __restrict__ x,
                            const float* __restrict__ W,
                            const float* __restrict__ bias,
                            float* __restrict__ out, int Co) {
    const int n0 = blockIdx.x * 128;
    const int o0 = blockIdx.y * 64;
    const int b  = blockIdx.z;
    __shared__ float xs[32][128];
    __shared__ float ws[64][33];
    const int t  = threadIdx.x;
    const int ox = t & 15;    // o direction (x16)
    const int ny = t >> 4;    // n direction (x16)
    float acc[8][4] = {};
    const float* xb = x + (size_t)b * Cch * Np;

    for (int c0 = 0; c0 < Cch; c0 += 32) {
        #pragma unroll
        for (int r = 0; r < 16; r++) {               // 32x128 = 4096 elems
            int l = t + 256 * r;
            int cc = l >> 7, nn = l & 127;
            xs[cc][nn] = xb[(size_t)(c0 + cc) * Np + n0 + nn];
        }
        #pragma unroll
        for (int r = 0; r < 8; r++) {                // 64x32 = 2048 elems
            int l = t + 256 * r;
            int oo = l >> 5, cc = l & 31;
            ws[oo][cc] = W[(o0 + oo) * Cch + c0 + cc];
        }
        __syncthreads();
        #pragma unroll
        for (int cc = 0; cc < 32; cc++) {
            float a[8], bb[4];
            #pragma unroll
            for (int i = 0; i < 8; i++) a[i] = xs[cc][ny + 16 * i];
            #pragma unroll
            for (int j = 0; j < 4; j++) bb[j] = ws[ox + 16 * j][cc];
            #pragma unroll
            for (int i = 0; i < 8; i++)
                #pragma unroll
                for (int j = 0; j < 4; j++) acc[i][j] += a[i] * bb[j];
        }
        __syncthreads();
    }
    #pragma unroll
    for (int j = 0; j < 4; j++) {
        float bv = bias[o0 + ox + 16 * j];
        #pragma unroll
        for (int i = 0; i < 8; i++) {
            int n = n0 + ny + 16 * i;
            out[((size_t)b * Np + n) * Co + o0 + ox + 16 * j] = acc[i][j] + bv;
        }
    }
}

// ---------------------------------------------------------------------------
// sim[b][n][m] = sum_o q[b][n][o] * k[b][m][o]
// Tile 128n x 128m, K-chunk 32 (Cq=64 -> 2 iters). 8x8 microtile.
// tx -> m (coalesced store), ty -> n.
// ---------------------------------------------------------------------------
__global__ void sim_kernel(const float* __restrict__ q,
                           const float* __restrict__ k,
                           float* __restrict__ S) {
    const int m0 = blockIdx.x * 128;
    const int n0 = blockIdx.y * 128;
    const int b  = blockIdx.z;
    __shared__ float qs[128][33];
    __shared__ float ks[128][33];
    const int t  = threadIdx.x;
    const int tx = t & 15;    // m
    const int ty = t >> 4;    // n
    float acc[8][8] = {};
    const float* qb = q + ((size_t)b * Np + n0) * Cqd;
    const float* kb = k + ((size_t)b * Np + m0) * Cqd;

    for (int c0 = 0; c0 < Cqd; c0 += 32) {
        #pragma unroll
        for (int r = 0; r < 16; r++) {               // 128x32 each
            int l = t + 256 * r;
            int oo = l & 31, nn = l >> 5;
            qs[nn][oo] = qb[nn * Cqd + c0 + oo];
            ks[nn][oo] = kb[nn * Cqd + c0 + oo];
        }
        __syncthreads();
        #pragma unroll
        for (int cc = 0; cc < 32; cc++) {
            float a[8], bb[8];
            #pragma unroll
            for (int i = 0; i < 8; i++) a[i] = qs[ty + 16 * i][cc];
            #pragma unroll
            for (int j = 0; j < 8; j++) bb[j] = ks[tx + 16 * j][cc];
            #pragma unroll
            for (int i = 0; i < 8; i++)
                #pragma unroll
                for (int j = 0; j < 8; j++) acc[i][j] += a[i] * bb[j];
        }
        __syncthreads();
    }
    float* Sb = S + ((size_t)b * Np + n0) * Np + m0;
    #pragma unroll
    for (int i = 0; i < 8; i++)
        #pragma unroll
        for (int j = 0; j < 8; j++)
            Sb[(size_t)(ty + 16 * i) * Np + tx + 16 * j] = acc[i][j];
}

// ---------------------------------------------------------------------------
// Row softmax in-place. One block per (row, b). Row (16 KB) lives in smem.
// ---------------------------------------------------------------------------
__global__ void softmax_kernel(float* __restrict__ S) {
    const int row = blockIdx.x;
    const int b   = blockIdx.y;
    float* p = S + ((size_t)b * Np + row) * Np;
    __shared__ float buf[Np];
    __shared__ float red[256];
    const int t = threadIdx.x;
    float4* p4 = (float4*)p;
    float4* b4 = (float4*)buf;

    float lmax = -1e30f;
    #pragma unroll
    for (int r = 0; r < 4; r++) {
        float4 v = p4[t + 256 * r];
        b4[t + 256 * r] = v;
        lmax = fmaxf(lmax, fmaxf(fmaxf(v.x, v.y), fmaxf(v.z, v.w)));
    }
    red[t] = lmax;
    __syncthreads();
    for (int s = 128; s > 0; s >>= 1) {
        if (t < s) red[t] = fmaxf(red[t], red[t + s]);
        __syncthreads();
    }
    const float mx = red[0];
    __syncthreads();

    float lsum = 0.f;
    #pragma unroll
    for (int r = 0; r < 4; r++) {
        float4 v = b4[t + 256 * r];
        v.x = __expf(v.x - mx); v.y = __expf(v.y - mx);
        v.z = __expf(v.z - mx); v.w = __expf(v.w - mx);
        b4[t + 256 * r] = v;
        lsum += v.x + v.y + v.z + v.w;
    }
    red[t] = lsum;
    __syncthreads();
    for (int s = 128; s > 0; s >>= 1) {
        if (t < s) red[t] += red[t + s];
        __syncthreads();
    }
    const float inv = 1.0f / red[0];
    __syncthreads();
    #pragma unroll
    for (int r = 0; r < 4; r++) {
        float4 v = b4[t + 256 * r];
        v.x *= inv; v.y *= inv; v.z *= inv; v.w *= inv;
        p4[t + 256 * r] = v;
    }
}

// ---------------------------------------------------------------------------
// ctx[b][n][c] = sum_m P[b][n][m] * V[b][m][c];  out[b][c][n] = g*ctx + x
// Tile 128n x 128c, K-chunk 32 m. tx -> n (coalesced out), ty -> c.
// ---------------------------------------------------------------------------
__global__ void ctx_kernel(const float* __restrict__ P,
                           const float* __restrict__ V,
                           const float* __restrict__ x,
                           const float* __restrict__ gamma,
                           float* __restrict__ out) {
    const int n0 = blockIdx.x * 128;
    const int c0 = blockIdx.y * 128;
    const int b  = blockIdx.z;
    __shared__ float ps[128][33];
    __shared__ float vs[32][128];
    const int t  = threadIdx.x;
    const int tx = t & 15;    // n
    const int ty = t >> 4;    // c
    float acc[8][8] = {};
    const float* Pb = P + ((size_t)b * Np + n0) * Np;
    const float* Vb = V + (size_t)b * Np * Cch + c0;

    for (int m0 = 0; m0 < Np; m0 += 32) {
        #pragma unroll
        for (int r = 0; r < 16; r++) {               // P tile 128x32
            int l = t + 256 * r;
            int mm = l & 31, nn = l >> 5;
            ps[nn][mm] = Pb[(size_t)nn * Np + m0 + mm];
        }
        #pragma unroll
        for (int r = 0; r < 16; r++) {               // V tile 32x128
            int l = t + 256 * r;
            int cv = l & 127, mm = l >> 7;
            vs[mm][cv] = Vb[(size_t)(m0 + mm) * Cch + cv];
        }
        __syncthreads();
        #pragma unroll
        for (int mm = 0; mm < 32; mm++) {
            float a[8], bb[8];
            #pragma unroll
            for (int i = 0; i < 8; i++) a[i] = ps[tx + 16 * i][mm];
            #pragma unroll
            for (int j = 0; j < 8; j++) bb[j] = vs[mm][ty + 16 * j];
            #pragma unroll
            for (int i = 0; i < 8; i++)
                #pragma unroll
                for (int j = 0; j < 8; j++) acc[i][j] += a[i] * bb[j];
        }
        __syncthreads();
    }
    const float g = gamma[0];
    #pragma unroll
    for (int j = 0; j < 8; j++) {
        int c = c0 + ty + 16 * j;
        #pragma unroll
        for (int i = 0; i < 8; i++) {
            int n = n0 + tx + 16 * i;
            size_t idx = ((size_t)b * Cch + c) * Np + n;
            out[idx] = g * acc[i][j] + x[idx];
        }
    }
}

// ---------------------------------------------------------------------------
extern "C" void kernel_launch(void* const* d_in, const int* in_sizes, int n_in,
                              void* d_out, int out_size) {
    const float* x     = (const float*)d_in[0];
    const float* Wq    = (const float*)d_in[1];
    const float* bq    = (const float*)d_in[2];
    const float* Wk    = (const float*)d_in[3];
    const float* bk    = (const float*)d_in[4];
    const float* Wv    = (const float*)d_in[5];
    const float* bv    = (const float*)d_in[6];
    const float* gamma = (const float*)d_in[7];
    float* out = (float*)d_out;

    float *q, *k, *v, *S;
    cudaGetSymbolAddress((void**)&q, g_q);
    cudaGetSymbolAddress((void**)&k, g_k);
    cudaGetSymbolAddress((void**)&v, g_v);
    cudaGetSymbolAddress((void**)&S, g_s);

    dim3 thr(256);
    proj_kernel<<<dim3(Np / 128, 1, Bsz), thr>>>(x, Wq, bq, q, Cqd);
    proj_kernel<<<dim3(Np / 128, 1, Bsz), thr>>>(x, Wk, bk, k, Cqd);
    proj_kernel<<<dim3(Np / 128, Cch / 64, Bsz), thr>>>(x, Wv, bv, v, Cch);
    sim_kernel<<<dim3(Np / 128, Np / 128, Bsz), thr>>>(q, k, S);
    softmax_kernel<<<dim3(Np, Bsz), thr>>>(S);
    ctx_kernel<<<dim3(Np / 128, Cch / 128, Bsz), thr>>>(S, v, x, gamma, out);
}

// round 3
// speedup vs baseline: 2.5758x; 2.5758x over previous
#include <cuda_runtime.h>

// Problem constants
#define Bsz 4
#define Cch 512
#define Np  4096     // H*W = 64*64
#define Cqd 64

// Scratch (device globals; allocation-free per harness rules)
__device__ float g_q[Bsz * Np * Cqd];                       // [B][N][Cq]   4 MB
__device__ float g_k[Bsz * Np * Cqd];                       // [B][N][Cq]   4 MB
__device__ float g_v[Bsz * Np * Cch];                       // [B][N][C]   32 MB
__device__ float g_s[(size_t)Bsz * Np * Np];                // [B][N][N]  256 MB

__device__ __forceinline__ unsigned f2tf32(float f) {
    unsigned u;
    asm("cvt.rna.tf32.f32 %0, %1;" : "=r"(u) : "f"(f));
    return u;
}

__device__ __forceinline__ void mma_tf32(float* d, const unsigned* a, const unsigned* b) {
    asm volatile(
        "mma.sync.aligned.m16n8k8.row.col.f32.tf32.tf32.f32 "
        "{%0,%1,%2,%3}, {%4,%5,%6,%7}, {%8,%9}, {%0,%1,%2,%3};\n"
        : "+f"(d[0]), "+f"(d[1]), "+f"(d[2]), "+f"(d[3])
        : "r"(a[0]), "r"(a[1]), "r"(a[2]), "r"(a[3]), "r"(b[0]), "r"(b[1]));
}

// ---------------------------------------------------------------------------
// Projection: out[b][n][o] = sum_c W[o][c] * x[b][c][n] + bias[o]   (fp32)
// ---------------------------------------------------------------------------
__global__ void proj_kernel(const float* __restrict__ x,
                            const float* __restrict__ W,
                            const float* __restrict__ bias,
                            float* __restrict__ out, int Co) {
    const int n0 = blockIdx.x * 128;
    const int o0 = blockIdx.y * 64;
    const int b  = blockIdx.z;
    __shared__ float xs[32][128];
    __shared__ float ws[64][33];
    const int t  = threadIdx.x;
    const int ox = t & 15;
    const int ny = t >> 4;
    float acc[8][4] = {};
    const float* xb = x + (size_t)b * Cch * Np;

    for (int c0 = 0; c0 < Cch; c0 += 32) {
        #pragma unroll
        for (int r = 0; r < 16; r++) {
            int l = t + 256 * r;
            int cc = l >> 7, nn = l & 127;
            xs[cc][nn] = xb[(size_t)(c0 + cc) * Np + n0 + nn];
        }
        #pragma unroll
        for (int r = 0; r < 8; r++) {
            int l = t + 256 * r;
            int oo = l >> 5, cc = l & 31;
            ws[oo][cc] = W[(o0 + oo) * Cch + c0 + cc];
        }
        __syncthreads();
        #pragma unroll
        for (int cc = 0; cc < 32; cc++) {
            float a[8], bb[4];
            #pragma unroll
            for (int i = 0; i < 8; i++) a[i] = xs[cc][ny + 16 * i];
            #pragma unroll
            for (int j = 0; j < 4; j++) bb[j] = ws[ox + 16 * j][cc];
            #pragma unroll
            for (int i = 0; i < 8; i++)
                #pragma unroll
                for (int j = 0; j < 4; j++) acc[i][j] += a[i] * bb[j];
        }
        __syncthreads();
    }
    #pragma unroll
    for (int j = 0; j < 4; j++) {
        float bv = bias[o0 + ox + 16 * j];
        #pragma unroll
        for (int i = 0; i < 8; i++) {
            int n = n0 + ny + 16 * i;
            out[((size_t)b * Np + n) * Co + o0 + ox + 16 * j] = acc[i][j] + bv;
        }
    }
}

// ---------------------------------------------------------------------------
// sim[b][n][m] = sum_o q[b][n][o] * k[b][m][o]   (fp32 -- precision-critical)
// ---------------------------------------------------------------------------
__global__ void sim_kernel(const float* __restrict__ q,
                           const float* __restrict__ k,
                           float* __restrict__ S) {
    const int m0 = blockIdx.x * 128;
    const int n0 = blockIdx.y * 128;
    const int b  = blockIdx.z;
    __shared__ float qs[128][33];
    __shared__ float ks[128][33];
    const int t  = threadIdx.x;
    const int tx = t & 15;
    const int ty = t >> 4;
    float acc[8][8] = {};
    const float* qb = q + ((size_t)b * Np + n0) * Cqd;
    const float* kb = k + ((size_t)b * Np + m0) * Cqd;

    for (int c0 = 0; c0 < Cqd; c0 += 32) {
        #pragma unroll
        for (int r = 0; r < 16; r++) {
            int l = t + 256 * r;
            int oo = l & 31, nn = l >> 5;
            qs[nn][oo] = qb[nn * Cqd + c0 + oo];
            ks[nn][oo] = kb[nn * Cqd + c0 + oo];
        }
        __syncthreads();
        #pragma unroll
        for (int cc = 0; cc < 32; cc++) {
            float a[8], bb[8];
            #pragma unroll
            for (int i = 0; i < 8; i++) a[i] = qs[ty + 16 * i][cc];
            #pragma unroll
            for (int j = 0; j < 8; j++) bb[j] = ks[tx + 16 * j][cc];
            #pragma unroll
            for (int i = 0; i < 8; i++)
                #pragma unroll
                for (int j = 0; j < 8; j++) acc[i][j] += a[i] * bb[j];
        }
        __syncthreads();
    }
    float* Sb = S + ((size_t)b * Np + n0) * Np + m0;
    #pragma unroll
    for (int i = 0; i < 8; i++)
        #pragma unroll
        for (int j = 0; j < 8; j++)
            Sb[(size_t)(ty + 16 * i) * Np + tx + 16 * j] = acc[i][j];
}

// ---------------------------------------------------------------------------
// Row softmax in-place (fp32).
// ---------------------------------------------------------------------------
__global__ void softmax_kernel(float* __restrict__ S) {
    const int row = blockIdx.x;
    const int b   = blockIdx.y;
    float* p = S + ((size_t)b * Np + row) * Np;
    __shared__ float buf[Np];
    __shared__ float red[256];
    const int t = threadIdx.x;
    float4* p4 = (float4*)p;
    float4* b4 = (float4*)buf;

    float lmax = -1e30f;
    #pragma unroll
    for (int r = 0; r < 4; r++) {
        float4 v = p4[t + 256 * r];
        b4[t + 256 * r] = v;
        lmax = fmaxf(lmax, fmaxf(fmaxf(v.x, v.y), fmaxf(v.z, v.w)));
    }
    red[t] = lmax;
    __syncthreads();
    for (int s = 128; s > 0; s >>= 1) {
        if (t < s) red[t] = fmaxf(red[t], red[t + s]);
        __syncthreads();
    }
    const float mx = red[0];
    __syncthreads();

    float lsum = 0.f;
    #pragma unroll
    for (int r = 0; r < 4; r++) {
        float4 v = b4[t + 256 * r];
        v.x = __expf(v.x - mx); v.y = __expf(v.y - mx);
        v.z = __expf(v.z - mx); v.w = __expf(v.w - mx);
        b4[t + 256 * r] = v;
        lsum += v.x + v.y + v.z + v.w;
    }
    red[t] = lsum;
    __syncthreads();
    for (int s = 128; s > 0; s >>= 1) {
        if (t < s) red[t] += red[t + s];
        __syncthreads();
    }
    const float inv = 1.0f / red[0];
    __syncthreads();
    #pragma unroll
    for (int r = 0; r < 4; r++) {
        float4 v = b4[t + 256 * r];
        v.x *= inv; v.y *= inv; v.z *= inv; v.w *= inv;
        p4[t + 256 * r] = v;
    }
}

// ---------------------------------------------------------------------------
// ctx via tf32 tensor cores:
//   ctx[b][n][c] = sum_m P[b][n][m] * V[b][m][c];  out[b][c][n] = g*ctx + x
// Block tile 128(n) x 128(c), K chunk 32(m), 8 warps (warp tile 64x32),
// double-buffered smem. Smem strides chosen conflict-free:
//   Ps[n][k] stride 36 -> bank = 4*row + k  (unique over a warp's A frag)
//   Vs[k][c] stride 136 -> bank = 8*k + col (unique over a warp's B frag)
// ---------------------------------------------------------------------------
#define PS_STRIDE 36
#define VS_STRIDE 136
#define PS_BUF (128 * PS_STRIDE)     // 4608
#define VS_BUF (32 * VS_STRIDE)      // 4352
#define CTX_SMEM ((2 * PS_BUF + 2 * VS_BUF) * 4)   // 71680 bytes

__global__ __launch_bounds__(256) void ctx_tc_kernel(
        const float* __restrict__ P,
        const float* __restrict__ V,
        const float* __restrict__ x,
        const float* __restrict__ gamma,
        float* __restrict__ out) {
    const int n0 = blockIdx.x * 128;
    const int c0 = blockIdx.y * 128;
    const int b  = blockIdx.z;

    extern __shared__ unsigned sm[];
    unsigned* Ps = sm;                 // [2][128][36]
    unsigned* Vs = sm + 2 * PS_BUF;    // [2][32][136]

    const int t    = threadIdx.x;
    const int wid  = t >> 5;
    const int lane = t & 31;
    const int gid  = lane >> 2;   // groupID
    const int tig  = lane & 3;    // thread-in-group
    const int wn   = (wid >> 2) * 64;   // warp n offset (0 or 64)
    const int wc   = (wid & 3) * 32;    // warp c offset (0..96)

    // Global staging addresses (fixed per thread; advance k each chunk)
    const int p_row = t >> 3;            // 0..31? no: 1024 float4 over 4 iters
    const int p_k4  = (t & 7) * 4;
    const int v_row = t >> 5;
    const int v_c4  = (t & 31) * 4;

    const float* Pb = P + ((size_t)b * Np + n0) * Np;          // + row*Np + k
    const float* Vb = V + (size_t)b * Np * Cch + c0;           // + row*Cch + c

    float acc[4][4][4] = {};
    float4 pst[4], vst[4];

    // ---- load chunk 0 into regs ----
    #pragma unroll
    for (int r = 0; r < 4; r++) {
        int l4 = t + 256 * r;
        pst[r] = *(const float4*)(Pb + (size_t)(l4 >> 3) * Np + (l4 & 7) * 4);
        vst[r] = *(const float4*)(Vb + (size_t)(l4 >> 5) * Cch + (l4 & 31) * 4);
    }
    // ---- store to smem buf 0 ----
    #pragma unroll
    for (int r = 0; r < 4; r++) {
        int l4 = t + 256 * r;
        unsigned* pd = Ps + (l4 >> 3) * PS_STRIDE + (l4 & 7) * 4;
        pd[0] = f2tf32(pst[r].x); pd[1] = f2tf32(pst[r].y);
        pd[2] = f2tf32(pst[r].z); pd[3] = f2tf32(pst[r].w);
        unsigned* vd = Vs + (l4 >> 5) * VS_STRIDE + (l4 & 31) * 4;
        vd[0] = f2tf32(vst[r].x); vd[1] = f2tf32(vst[r].y);
        vd[2] = f2tf32(vst[r].z); vd[3] = f2tf32(vst[r].w);
    }
    __syncthreads();

    const int NI = Np / 32;  // 128 chunks
    for (int it = 0; it < NI; it++) {
        const int cur = it & 1;
        // prefetch next chunk to regs
        if (it + 1 < NI) {
            const float* Pn = Pb + (it + 1) * 32;
            const float* Vn = Vb + (size_t)(it + 1) * 32 * Cch;
            #pragma unroll
            for (int r = 0; r < 4; r++) {
                int l4 = t + 256 * r;
                pst[r] = *(const float4*)(Pn + (size_t)(l4 >> 3) * Np + (l4 & 7) * 4);
                vst[r] = *(const float4*)(Vn + (size_t)(l4 >> 5) * Cch + (l4 & 31) * 4);
            }
        }
        // compute on cur
        const unsigned* Pc = Ps + cur * PS_BUF;
        const unsigned* Vc = Vs + cur * VS_BUF;
        #pragma unroll
        for (int ks = 0; ks < 4; ks++) {
            const int kb = ks * 8;
            unsigned afr[4][4];
            #pragma unroll
            for (int mt = 0; mt < 4; mt++) {
                int row = wn + mt * 16 + gid;
                afr[mt][0] = Pc[row * PS_STRIDE + kb + tig];
                afr[mt][1] = Pc[(row + 8) * PS_STRIDE + kb + tig];
                afr[mt][2] = Pc[row * PS_STRIDE + kb + tig + 4];
                afr[mt][3] = Pc[(row + 8) * PS_STRIDE + kb + tig + 4];
            }
            unsigned bfr[4][2];
            #pragma unroll
            for (int nt = 0; nt < 4; nt++) {
                int col = wc + nt * 8 + gid;
                bfr[nt][0] = Vc[(kb + tig) * VS_STRIDE + col];
                bfr[nt][1] = Vc[(kb + tig + 4) * VS_STRIDE + col];
            }
            #pragma unroll
            for (int mt = 0; mt < 4; mt++)
                #pragma unroll
                for (int nt = 0; nt < 4; nt++)
                    mma_tf32(acc[mt][nt], afr[mt], bfr[nt]);
        }
        // store prefetched chunk to other buffer
        if (it + 1 < NI) {
            unsigned* Pd = Ps + (cur ^ 1) * PS_BUF;
            unsigned* Vd = Vs + (cur ^ 1) * VS_BUF;
            #pragma unroll
            for (int r = 0; r < 4; r++) {
                int l4 = t + 256 * r;
                unsigned* pd = Pd + (l4 >> 3) * PS_STRIDE + (l4 & 7) * 4;
                pd[0] = f2tf32(pst[r].x); pd[1] = f2tf32(pst[r].y);
                pd[2] = f2tf32(pst[r].z); pd[3] = f2tf32(pst[r].w);
                unsigned* vd = Vd + (l4 >> 5) * VS_STRIDE + (l4 & 31) * 4;
                vd[0] = f2tf32(vst[r].x); vd[1] = f2tf32(vst[r].y);
                vd[2] = f2tf32(vst[r].z); vd[3] = f2tf32(vst[r].w);
            }
            __syncthreads();
        }
    }

    // Epilogue: out[b][c][n] = g*ctx + x
    const float g = gamma[0];
    #pragma unroll
    for (int mt = 0; mt < 4; mt++) {
        int n = n0 + wn + mt * 16 + gid;
        #pragma unroll
        for (int nt = 0; nt < 4; nt++) {
            int c = c0 + wc + nt * 8 + 2 * tig;
            size_t i00 = ((size_t)b * Cch + c) * Np + n;
            size_t i01 = ((size_t)b * Cch + c + 1) * Np + n;
            out[i00]     = g * acc[mt][nt][0] + x[i00];
            out[i01]     = g * acc[mt][nt][1] + x[i01];
            out[i00 + 8] = g * acc[mt][nt][2] + x[i00 + 8];
            out[i01 + 8] = g * acc[mt][nt][3] + x[i01 + 8];
        }
    }
}

// ---------------------------------------------------------------------------
extern "C" void kernel_launch(void* const* d_in, const int* in_sizes, int n_in,
                              void* d_out, int out_size) {
    const float* x     = (const float*)d_in[0];
    const float* Wq    = (const float*)d_in[1];
    const float* bq    = (const float*)d_in[2];
    const float* Wk    = (const float*)d_in[3];
    const float* bk    = (const float*)d_in[4];
    const float* Wv    = (const float*)d_in[5];
    const float* bv    = (const float*)d_in[6];
    const float* gamma = (const float*)d_in[7];
    float* out = (float*)d_out;

    float *q, *k, *v, *S;
    cudaGetSymbolAddress((void**)&q, g_q);
    cudaGetSymbolAddress((void**)&k, g_k);
    cudaGetSymbolAddress((void**)&v, g_v);
    cudaGetSymbolAddress((void**)&S, g_s);

    static int smem_set = 0;
    if (!smem_set) {
        cudaFuncSetAttribute(ctx_tc_kernel,
                             cudaFuncAttributeMaxDynamicSharedMemorySize, CTX_SMEM);
        smem_set = 1;
    }

    dim3 thr(256);
    proj_kernel<<<dim3(Np / 128, 1, Bsz), thr>>>(x, Wq, bq, q, Cqd);
    proj_kernel<<<dim3(Np / 128, 1, Bsz), thr>>>(x, Wk, bk, k, Cqd);
    proj_kernel<<<dim3(Np / 128, Cch / 64, Bsz), thr>>>(x, Wv, bv, v, Cch);
    sim_kernel<<<dim3(Np / 128, Np / 128, Bsz), thr>>>(q, k, S);
    softmax_kernel<<<dim3(Np, Bsz), thr>>>(S);
    ctx_tc_kernel<<<dim3(Np / 128, Cch / 128, Bsz), thr, CTX_SMEM>>>(S, v, x, gamma, out);
}

// round 5
// speedup vs baseline: 3.5031x; 1.3600x over previous
#include <cuda_runtime.h>

// Problem constants
#define Bsz 4
#define Cch 512
#define Np  4096     // H*W = 64*64
#define Cqd 64

// Scratch (device globals; allocation-free per harness rules)
__device__ float g_q[Bsz * Np * Cqd];                       // [B][N][Cq]   4 MB
__device__ float g_k[Bsz * Np * Cqd];                       // [B][N][Cq]   4 MB
__device__ float g_v[Bsz * Np * Cch];                       // [B][N][C]   32 MB
__device__ float g_s[(size_t)Bsz * Np * Np];                // [B][N][N]  256 MB

__device__ __forceinline__ unsigned f2tf32(float f) {
    unsigned u;
    asm("cvt.rna.tf32.f32 %0, %1;" : "=r"(u) : "f"(f));
    return u;
}

__device__ __forceinline__ void split_tf32(float v, unsigned& hi, unsigned& lo) {
    unsigned h = f2tf32(v);
    hi = h;
    lo = f2tf32(v - __uint_as_float(h));
}

__device__ __forceinline__ void mma_tf32(float* d, const unsigned* a, const unsigned* b) {
    asm volatile(
        "mma.sync.aligned.m16n8k8.row.col.f32.tf32.tf32.f32 "
        "{%0,%1,%2,%3}, {%4,%5,%6,%7}, {%8,%9}, {%0,%1,%2,%3};\n"
        : "+f"(d[0]), "+f"(d[1]), "+f"(d[2]), "+f"(d[3])
        : "r"(a[0]), "r"(a[1]), "r"(a[2]), "r"(a[3]), "r"(b[0]), "r"(b[1]));
}

// ---------------------------------------------------------------------------
// fp32 projection (used for Q and K only; tiny: Cq=64)
// out[b][n][o] = sum_c W[o][c] * x[b][c][n] + bias[o]
// ---------------------------------------------------------------------------
__global__ void proj_kernel(const float* __restrict__ x,
                            const float* __restrict__ W,
                            const float* __restrict__ bias,
                            float* __restrict__ out, int Co) {
    const int n0 = blockIdx.x * 128;
    const int o0 = blockIdx.y * 64;
    const int b  = blockIdx.z;
    __shared__ float xs[32][128];
    __shared__ float ws[64][33];
    const int t  = threadIdx.x;
    const int ox = t & 15;
    const int ny = t >> 4;
    float acc[8][4] = {};
    const float* xb = x + (size_t)b * Cch * Np;

    for (int c0 = 0; c0 < Cch; c0 += 32) {
        #pragma unroll
        for (int r = 0; r < 16; r++) {
            int l = t + 256 * r;
            int cc = l >> 7, nn = l & 127;
            xs[cc][nn] = xb[(size_t)(c0 + cc) * Np + n0 + nn];
        }
        #pragma unroll
        for (int r = 0; r < 8; r++) {
            int l = t + 256 * r;
            int oo = l >> 5, cc = l & 31;
            ws[oo][cc] = W[(o0 + oo) * Cch + c0 + cc];
        }
        __syncthreads();
        #pragma unroll
        for (int cc = 0; cc < 32; cc++) {
            float a[8], bb[4];
            #pragma unroll
            for (int i = 0; i < 8; i++) a[i] = xs[cc][ny + 16 * i];
            #pragma unroll
            for (int j = 0; j < 4; j++) bb[j] = ws[ox + 16 * j][cc];
            #pragma unroll
            for (int i = 0; i < 8; i++)
                #pragma unroll
                for (int j = 0; j < 4; j++) acc[i][j] += a[i] * bb[j];
        }
        __syncthreads();
    }
    #pragma unroll
    for (int j = 0; j < 4; j++) {
        float bv = bias[o0 + ox + 16 * j];
        #pragma unroll
        for (int i = 0; i < 8; i++) {
            int n = n0 + ny + 16 * i;
            out[((size_t)b * Np + n) * Co + o0 + ox + 16 * j] = acc[i][j] + bv;
        }
    }
}

// ---------------------------------------------------------------------------
// V projection via tf32 MMA.
//   v[b][n][c] = sum_k Wv[c][k] * x[b][k][n] + bv[c]
// Tile 128c x 128n, K chunk 32, double-buffered.
// ---------------------------------------------------------------------------
#define WS_STRIDE 36
#define XS_STRIDE 136
#define WS_BUF (128 * WS_STRIDE)     // 4608
#define XS_BUF (32 * XS_STRIDE)      // 4352
#define VP_SMEM ((2 * WS_BUF + 2 * XS_BUF) * 4)   // 71680 bytes

__global__ __launch_bounds__(256) void vproj_tc_kernel(
        const float* __restrict__ x,
        const float* __restrict__ W,
        const float* __restrict__ bias,
        float* __restrict__ out) {
    const int nB = blockIdx.x * 128;
    const int cB = blockIdx.y * 128;
    const int b  = blockIdx.z;

    extern __shared__ unsigned sm[];
    unsigned* Ws = sm;                 // [2][128][36]
    unsigned* Xs = sm + 2 * WS_BUF;    // [2][32][136]

    const int t    = threadIdx.x;
    const int wid  = t >> 5;
    const int lane = t & 31;
    const int gid  = lane >> 2;
    const int tig  = lane & 3;
    const int wc   = (wid >> 2) * 64;
    const int wn   = (wid & 3) * 32;

    const float* xb = x + (size_t)b * Cch * Np;   // [k][n]

    float acc[4][4][4] = {};
    float4 wst[4], xst[4];

    #pragma unroll
    for (int r = 0; r < 4; r++) {
        int l4 = t + 256 * r;
        wst[r] = *(const float4*)(W + (size_t)(cB + (l4 >> 3)) * Cch + (l4 & 7) * 4);
        xst[r] = *(const float4*)(xb + (size_t)(l4 >> 5) * Np + nB + (l4 & 31) * 4);
    }
    #pragma unroll
    for (int r = 0; r < 4; r++) {
        int l4 = t + 256 * r;
        unsigned* wd = Ws + (l4 >> 3) * WS_STRIDE + (l4 & 7) * 4;
        wd[0] = f2tf32(wst[r].x); wd[1] = f2tf32(wst[r].y);
        wd[2] = f2tf32(wst[r].z); wd[3] = f2tf32(wst[r].w);
        unsigned* xd = Xs + (l4 >> 5) * XS_STRIDE + (l4 & 31) * 4;
        xd[0] = f2tf32(xst[r].x); xd[1] = f2tf32(xst[r].y);
        xd[2] = f2tf32(xst[r].z); xd[3] = f2tf32(xst[r].w);
    }
    __syncthreads();

    const int NI = Cch / 32;   // 16
    for (int it = 0; it < NI; it++) {
        const int cur = it & 1;
        if (it + 1 < NI) {
            const int c0 = (it + 1) * 32;
            #pragma unroll
            for (int r = 0; r < 4; r++) {
                int l4 = t + 256 * r;
                wst[r] = *(const float4*)(W + (size_t)(cB + (l4 >> 3)) * Cch + c0 + (l4 & 7) * 4);
                xst[r] = *(const float4*)(xb + (size_t)(c0 + (l4 >> 5)) * Np + nB + (l4 & 31) * 4);
            }
        }
        const unsigned* Wc = Ws + cur * WS_BUF;
        const unsigned* Xc = Xs + cur * XS_BUF;
        #pragma unroll
        for (int ks = 0; ks < 4; ks++) {
            const int kb = ks * 8;
            unsigned afr[4][4];
            #pragma unroll
            for (int mt = 0; mt < 4; mt++) {
                int row = wc + mt * 16 + gid;
                afr[mt][0] = Wc[row * WS_STRIDE + kb + tig];
                afr[mt][1] = Wc[(row + 8) * WS_STRIDE + kb + tig];
                afr[mt][2] = Wc[row * WS_STRIDE + kb + tig + 4];
                afr[mt][3] = Wc[(row + 8) * WS_STRIDE + kb + tig + 4];
            }
            unsigned bfr[4][2];
            #pragma unroll
            for (int nt = 0; nt < 4; nt++) {
                int col = wn + nt * 8 + gid;
                bfr[nt][0] = Xc[(kb + tig) * XS_STRIDE + col];
                bfr[nt][1] = Xc[(kb + tig + 4) * XS_STRIDE + col];
            }
            #pragma unroll
            for (int mt = 0; mt < 4; mt++)
                #pragma unroll
                for (int nt = 0; nt < 4; nt++)
                    mma_tf32(acc[mt][nt], afr[mt], bfr[nt]);
        }
        if (it + 1 < NI) {
            unsigned* Wd = Ws + (cur ^ 1) * WS_BUF;
            unsigned* Xd = Xs + (cur ^ 1) * XS_BUF;
            #pragma unroll
            for (int r = 0; r < 4; r++) {
                int l4 = t + 256 * r;
                unsigned* wd = Wd + (l4 >> 3) * WS_STRIDE + (l4 & 7) * 4;
                wd[0] = f2tf32(wst[r].x); wd[1] = f2tf32(wst[r].y);
                wd[2] = f2tf32(wst[r].z); wd[3] = f2tf32(wst[r].w);
                unsigned* xd = Xd + (l4 >> 5) * XS_STRIDE + (l4 & 31) * 4;
                xd[0] = f2tf32(xst[r].x); xd[1] = f2tf32(xst[r].y);
                xd[2] = f2tf32(xst[r].z); xd[3] = f2tf32(xst[r].w);
            }
            __syncthreads();
        }
    }

    // Epilogue: out[b][n][c] = acc + bias[c]
    float* ob = out + (size_t)b * Np * Cch;
    #pragma unroll
    for (int mt = 0; mt < 4; mt++) {
        int c = cB + wc + mt * 16 + gid;
        float b0 = bias[c], b1 = bias[c + 8];
        #pragma unroll
        for (int nt = 0; nt < 4; nt++) {
            int n = nB + wn + nt * 8 + 2 * tig;
            ob[(size_t)n * Cch + c]           = acc[mt][nt][0] + b0;
            ob[(size_t)(n + 1) * Cch + c]     = acc[mt][nt][1] + b0;
            ob[(size_t)n * Cch + c + 8]       = acc[mt][nt][2] + b1;
            ob[(size_t)(n + 1) * Cch + c + 8] = acc[mt][nt][3] + b1;
        }
    }
}

// ---------------------------------------------------------------------------
// sim via 3xTF32 split-precision MMA (fp32-equivalent accuracy):
//   sim[b][n][m] = sum_o q[b][n][o] * k[b][m][o]
// K=64 processed as TWO 32-column chunk passes so the stride-36
// conflict-free layout holds (round-4 bug: 64 cols stored into stride-36
// rows overran the smem allocation).
// ---------------------------------------------------------------------------
#define QS_STRIDE 36
#define QS_BUF (128 * QS_STRIDE)                  // 4608 words
#define SIM_SMEM (4 * QS_BUF * 4)                 // 73728 bytes

__global__ __launch_bounds__(256) void sim_tc_kernel(
        const float* __restrict__ q,
        const float* __restrict__ k,
        float* __restrict__ S) {
    const int m0 = blockIdx.x * 128;
    const int n0 = blockIdx.y * 128;
    const int b  = blockIdx.z;

    extern __shared__ unsigned sm[];
    unsigned* qh = sm;                // [128][36]
    unsigned* ql = sm + QS_BUF;
    unsigned* kh = sm + 2 * QS_BUF;
    unsigned* kl = sm + 3 * QS_BUF;

    const int t    = threadIdx.x;
    const int wid  = t >> 5;
    const int lane = t & 31;
    const int gid  = lane >> 2;
    const int tig  = lane & 3;
    const int wn   = (wid >> 2) * 64;   // n offset
    const int wm   = (wid & 3) * 32;    // m offset

    const float* qb = q + ((size_t)b * Np + n0) * Cqd;
    const float* kb = k + ((size_t)b * Np + m0) * Cqd;

    float acc[4][4][4] = {};

    for (int c0 = 0; c0 < Cqd; c0 += 32) {
        if (c0) __syncthreads();   // previous chunk's compute done before overwrite
        // Load + split one 128x32 chunk of q and k
        #pragma unroll
        for (int r = 0; r < 4; r++) {
            int l4 = t + 256 * r;
            int row = l4 >> 3, j4 = (l4 & 7) * 4;
            float4 vq = *(const float4*)(qb + row * Cqd + c0 + j4);
            float4 vk = *(const float4*)(kb + row * Cqd + c0 + j4);
            unsigned* qhd = qh + row * QS_STRIDE + j4;
            unsigned* qld = ql + row * QS_STRIDE + j4;
            split_tf32(vq.x, qhd[0], qld[0]); split_tf32(vq.y, qhd[1], qld[1]);
            split_tf32(vq.z, qhd[2], qld[2]); split_tf32(vq.w, qhd[3], qld[3]);
            unsigned* khd = kh + row * QS_STRIDE + j4;
            unsigned* kld = kl + row * QS_STRIDE + j4;
            split_tf32(vk.x, khd[0], kld[0]); split_tf32(vk.y, khd[1], kld[1]);
            split_tf32(vk.z, khd[2], kld[2]); split_tf32(vk.w, khd[3], kld[3]);
        }
        __syncthreads();

        #pragma unroll
        for (int ks = 0; ks < 4; ks++) {
            const int kb8 = ks * 8;
            unsigned ah[4][4], al[4][4];
            #pragma unroll
            for (int mt = 0; mt < 4; mt++) {
                int row = wn + mt * 16 + gid;
                ah[mt][0] = qh[row * QS_STRIDE + kb8 + tig];
                ah[mt][1] = qh[(row + 8) * QS_STRIDE + kb8 + tig];
                ah[mt][2] = qh[row * QS_STRIDE + kb8 + tig + 4];
                ah[mt][3] = qh[(row + 8) * QS_STRIDE + kb8 + tig + 4];
                al[mt][0] = ql[row * QS_STRIDE + kb8 + tig];
                al[mt][1] = ql[(row + 8) * QS_STRIDE + kb8 + tig];
                al[mt][2] = ql[row * QS_STRIDE + kb8 + tig + 4];
                al[mt][3] = ql[(row + 8) * QS_STRIDE + kb8 + tig + 4];
            }
            unsigned bh[4][2], bl[4][2];
            #pragma unroll
            for (int nt = 0; nt < 4; nt++) {
                int col = wm + nt * 8 + gid;
                bh[nt][0] = kh[col * QS_STRIDE + kb8 + tig];
                bh[nt][1] = kh[col * QS_STRIDE + kb8 + tig + 4];
                bl[nt][0] = kl[col * QS_STRIDE + kb8 + tig];
                bl[nt][1] = kl[col * QS_STRIDE + kb8 + tig + 4];
            }
            #pragma unroll
            for (int mt = 0; mt < 4; mt++)
                #pragma unroll
                for (int nt = 0; nt < 4; nt++) {
                    mma_tf32(acc[mt][nt], ah[mt], bl[nt]);   // cross terms first
                    mma_tf32(acc[mt][nt], al[mt], bh[nt]);
                    mma_tf32(acc[mt][nt], ah[mt], bh[nt]);   // main term
                }
        }
    }

    // Store S (float2 pairs -> full 32B sectors)
    float* Sb = S + ((size_t)b * Np + n0) * Np + m0;
    #pragma unroll
    for (int mt = 0; mt < 4; mt++) {
        int n = wn + mt * 16 + gid;
        #pragma unroll
        for (int nt = 0; nt < 4; nt++) {
            int m = wm + nt * 8 + 2 * tig;
            *(float2*)(Sb + (size_t)n * Np + m)       = make_float2(acc[mt][nt][0], acc[mt][nt][1]);
            *(float2*)(Sb + (size_t)(n + 8) * Np + m) = make_float2(acc[mt][nt][2], acc[mt][nt][3]);
        }
    }
}

// ---------------------------------------------------------------------------
// Row softmax in-place (fp32).
// ---------------------------------------------------------------------------
__global__ void softmax_kernel(float* __restrict__ S) {
    const int row = blockIdx.x;
    const int b   = blockIdx.y;
    float* p = S + ((size_t)b * Np + row) * Np;
    __shared__ float buf[Np];
    __shared__ float red[256];
    const int t = threadIdx.x;
    float4* p4 = (float4*)p;
    float4* b4 = (float4*)buf;

    float lmax = -1e30f;
    #pragma unroll
    for (int r = 0; r < 4; r++) {
        float4 v = p4[t + 256 * r];
        b4[t + 256 * r] = v;
        lmax = fmaxf(lmax, fmaxf(fmaxf(v.x, v.y), fmaxf(v.z, v.w)));
    }
    red[t] = lmax;
    __syncthreads();
    for (int s = 128; s > 0; s >>= 1) {
        if (t < s) red[t] = fmaxf(red[t], red[t + s]);
        __syncthreads();
    }
    const float mx = red[0];
    __syncthreads();

    float lsum = 0.f;
    #pragma unroll
    for (int r = 0; r < 4; r++) {
        float4 v = b4[t + 256 * r];
        v.x = __expf(v.x - mx); v.y = __expf(v.y - mx);
        v.z = __expf(v.z - mx); v.w = __expf(v.w - mx);
        b4[t + 256 * r] = v;
        lsum += v.x + v.y + v.z + v.w;
    }
    red[t] = lsum;
    __syncthreads();
    for (int s = 128; s > 0; s >>= 1) {
        if (t < s) red[t] += red[t + s];
        __syncthreads();
    }
    const float inv = 1.0f / red[0];
    __syncthreads();
    #pragma unroll
    for (int r = 0; r < 4; r++) {
        float4 v = b4[t + 256 * r];
        v.x *= inv; v.y *= inv; v.z *= inv; v.w *= inv;
        p4[t + 256 * r] = v;
    }
}

// ---------------------------------------------------------------------------
// ctx via tf32 tensor cores:
//   ctx[b][n][c] = sum_m P[b][n][m] * V[b][m][c];  out[b][c][n] = g*ctx + x
// ---------------------------------------------------------------------------
#define PS_STRIDE 36
#define VS_STRIDE 136
#define PS_BUF (128 * PS_STRIDE)     // 4608
#define VS_BUF (32 * VS_STRIDE)      // 4352
#define CTX_SMEM ((2 * PS_BUF + 2 * VS_BUF) * 4)   // 71680 bytes

__global__ __launch_bounds__(256) void ctx_tc_kernel(
        const float* __restrict__ P,
        const float* __restrict__ V,
        const float* __restrict__ x,
        const float* __restrict__ gamma,
        float* __restrict__ out) {
    const int n0 = blockIdx.x * 128;
    const int c0 = blockIdx.y * 128;
    const int b  = blockIdx.z;

    extern __shared__ unsigned sm[];
    unsigned* Ps = sm;                 // [2][128][36]
    unsigned* Vs = sm + 2 * PS_BUF;    // [2][32][136]

    const int t    = threadIdx.x;
    const int wid  = t >> 5;
    const int lane = t & 31;
    const int gid  = lane >> 2;
    const int tig  = lane & 3;
    const int wn   = (wid >> 2) * 64;
    const int wc   = (wid & 3) * 32;

    const float* Pb = P + ((size_t)b * Np + n0) * Np;
    const float* Vb = V + (size_t)b * Np * Cch + c0;

    float acc[4][4][4] = {};
    float4 pst[4], vst[4];

    #pragma unroll
    for (int r = 0; r < 4; r++) {
        int l4 = t + 256 * r;
        pst[r] = *(const float4*)(Pb + (size_t)(l4 >> 3) * Np + (l4 & 7) * 4);
        vst[r] = *(const float4*)(Vb + (size_t)(l4 >> 5) * Cch + (l4 & 31) * 4);
    }
    #pragma unroll
    for (int r = 0; r < 4; r++) {
        int l4 = t + 256 * r;
        unsigned* pd = Ps + (l4 >> 3) * PS_STRIDE + (l4 & 7) * 4;
        pd[0] = f2tf32(pst[r].x); pd[1] = f2tf32(pst[r].y);
        pd[2] = f2tf32(pst[r].z); pd[3] = f2tf32(pst[r].w);
        unsigned* vd = Vs + (l4 >> 5) * VS_STRIDE + (l4 & 31) * 4;
        vd[0] = f2tf32(vst[r].x); vd[1] = f2tf32(vst[r].y);
        vd[2] = f2tf32(vst[r].z); vd[3] = f2tf32(vst[r].w);
    }
    __syncthreads();

    const int NI = Np / 32;
    for (int it = 0; it < NI; it++) {
        const int cur = it & 1;
        if (it + 1 < NI) {
            const float* Pn = Pb + (it + 1) * 32;
            const float* Vn = Vb + (size_t)(it + 1) * 32 * Cch;
            #pragma unroll
            for (int r = 0; r < 4; r++) {
                int l4 = t + 256 * r;
                pst[r] = *(const float4*)(Pn + (size_t)(l4 >> 3) * Np + (l4 & 7) * 4);
                vst[r] = *(const float4*)(Vn + (size_t)(l4 >> 5) * Cch + (l4 & 31) * 4);
            }
        }
        const unsigned* Pc = Ps + cur * PS_BUF;
        const unsigned* Vc = Vs + cur * VS_BUF;
        #pragma unroll
        for (int ks = 0; ks < 4; ks++) {
            const int kb = ks * 8;
            unsigned afr[4][4];
            #pragma unroll
            for (int mt = 0; mt < 4; mt++) {
                int row = wn + mt * 16 + gid;
                afr[mt][0] = Pc[row * PS_STRIDE + kb + tig];
                afr[mt][1] = Pc[(row + 8) * PS_STRIDE + kb + tig];
                afr[mt][2] = Pc[row * PS_STRIDE + kb + tig + 4];
                afr[mt][3] = Pc[(row + 8) * PS_STRIDE + kb + tig + 4];
            }
            unsigned bfr[4][2];
            #pragma unroll
            for (int nt = 0; nt < 4; nt++) {
                int col = wc + nt * 8 + gid;
                bfr[nt][0] = Vc[(kb + tig) * VS_STRIDE + col];
                bfr[nt][1] = Vc[(kb + tig + 4) * VS_STRIDE + col];
            }
            #pragma unroll
            for (int mt = 0; mt < 4; mt++)
                #pragma unroll
                for (int nt = 0; nt < 4; nt++)
                    mma_tf32(acc[mt][nt], afr[mt], bfr[nt]);
        }
        if (it + 1 < NI) {
            unsigned* Pd = Ps + (cur ^ 1) * PS_BUF;
            unsigned* Vd = Vs + (cur ^ 1) * VS_BUF;
            #pragma unroll
            for (int r = 0; r < 4; r++) {
                int l4 = t + 256 * r;
                unsigned* pd = Pd + (l4 >> 3) * PS_STRIDE + (l4 & 7) * 4;
                pd[0] = f2tf32(pst[r].x); pd[1] = f2tf32(pst[r].y);
                pd[2] = f2tf32(pst[r].z); pd[3] = f2tf32(pst[r].w);
                unsigned* vd = Vd + (l4 >> 5) * VS_STRIDE + (l4 & 31) * 4;
                vd[0] = f2tf32(vst[r].x); vd[1] = f2tf32(vst[r].y);
                vd[2] = f2tf32(vst[r].z); vd[3] = f2tf32(vst[r].w);
            }
            __syncthreads();
        }
    }

    const float g = gamma[0];
    #pragma unroll
    for (int mt = 0; mt < 4; mt++) {
        int n = n0 + wn + mt * 16 + gid;
        #pragma unroll
        for (int nt = 0; nt < 4; nt++) {
            int c = c0 + wc + nt * 8 + 2 * tig;
            size_t i00 = ((size_t)b * Cch + c) * Np + n;
            size_t i01 = ((size_t)b * Cch + c + 1) * Np + n;
            out[i00]     = g * acc[mt][nt][0] + x[i00];
            out[i01]     = g * acc[mt][nt][1] + x[i01];
            out[i00 + 8] = g * acc[mt][nt][2] + x[i00 + 8];
            out[i01 + 8] = g * acc[mt][nt][3] + x[i01 + 8];
        }
    }
}

// ---------------------------------------------------------------------------
extern "C" void kernel_launch(void* const* d_in, const int* in_sizes, int n_in,
                              void* d_out, int out_size) {
    const float* x     = (const float*)d_in[0];
    const float* Wq    = (const float*)d_in[1];
    const float* bq    = (const float*)d_in[2];
    const float* Wk    = (const float*)d_in[3];
    const float* bk    = (const float*)d_in[4];
    const float* Wv    = (const float*)d_in[5];
    const float* bv    = (const float*)d_in[6];
    const float* gamma = (const float*)d_in[7];
    float* out = (float*)d_out;

    float *q, *k, *v, *S;
    cudaGetSymbolAddress((void**)&q, g_q);
    cudaGetSymbolAddress((void**)&k, g_k);
    cudaGetSymbolAddress((void**)&v, g_v);
    cudaGetSymbolAddress((void**)&S, g_s);

    static int smem_set = 0;
    if (!smem_set) {
        cudaFuncSetAttribute(ctx_tc_kernel,
                             cudaFuncAttributeMaxDynamicSharedMemorySize, CTX_SMEM);
        cudaFuncSetAttribute(vproj_tc_kernel,
                             cudaFuncAttributeMaxDynamicSharedMemorySize, VP_SMEM);
        cudaFuncSetAttribute(sim_tc_kernel,
                             cudaFuncAttributeMaxDynamicSharedMemorySize, SIM_SMEM);
        smem_set = 1;
    }

    dim3 thr(256);
    proj_kernel<<<dim3(Np / 128, 1, Bsz), thr>>>(x, Wq, bq, q, Cqd);
    proj_kernel<<<dim3(Np / 128, 1, Bsz), thr>>>(x, Wk, bk, k, Cqd);
    vproj_tc_kernel<<<dim3(Np / 128, Cch / 128, Bsz), thr, VP_SMEM>>>(x, Wv, bv, v);
    sim_tc_kernel<<<dim3(Np / 128, Np / 128, Bsz), thr, SIM_SMEM>>>(q, k, S);
    softmax_kernel<<<dim3(Np, Bsz), thr>>>(S);
    ctx_tc_kernel<<<dim3(Np / 128, Cch / 128, Bsz), thr, CTX_SMEM>>>(S, v, x, gamma, out);
}

// round 10
// speedup vs baseline: 4.6093x; 1.3158x over previous
#include <cuda_runtime.h>
#include <cuda_bf16.h>
#include <cstdint>

// Problem constants
#define Bsz 4
#define Cch 512
#define Np  4096     // H*W = 64*64
#define Cqd 64

// Scratch (device globals; allocation-free per harness rules)
__device__ float g_q[Bsz * Np * Cqd];                       // [B][N][Cq]   4 MB
__device__ float g_k[Bsz * Np * Cqd];                       // [B][N][Cq]   4 MB
__device__ float g_s[(size_t)Bsz * Np * Np];                // sim fp32   256 MB
__device__ __nv_bfloat16 g_pb[(size_t)Bsz * Np * Np];       // P bf16     128 MB
__device__ __nv_bfloat16 g_vt[(size_t)Bsz * Cch * Np];      // V^T bf16    16 MB

// ---------------------------------------------------------------------------
// Helpers
// ---------------------------------------------------------------------------
__device__ __forceinline__ unsigned f2tf32(float f) {
    unsigned u;
    asm("cvt.rna.tf32.f32 %0, %1;" : "=r"(u) : "f"(f));
    return u;
}

__device__ __forceinline__ void split_tf32(float v, unsigned& hi, unsigned& lo) {
    unsigned h = f2tf32(v);
    hi = h;
    lo = f2tf32(v - __uint_as_float(h));
}

__device__ __forceinline__ void mma_tf32(float* d, const unsigned* a, const unsigned* b) {
    asm volatile(
        "mma.sync.aligned.m16n8k8.row.col.f32.tf32.tf32.f32 "
        "{%0,%1,%2,%3}, {%4,%5,%6,%7}, {%8,%9}, {%0,%1,%2,%3};\n"
        : "+f"(d[0]), "+f"(d[1]), "+f"(d[2]), "+f"(d[3])
        : "r"(a[0]), "r"(a[1]), "r"(a[2]), "r"(a[3]), "r"(b[0]), "r"(b[1]));
}

__device__ __forceinline__ void mma_bf16(float* d, const unsigned* a, const unsigned* b) {
    asm volatile(
        "mma.sync.aligned.m16n8k16.row.col.f32.bf16.bf16.f32 "
        "{%0,%1,%2,%3}, {%4,%5,%6,%7}, {%8,%9}, {%0,%1,%2,%3};\n"
        : "+f"(d[0]), "+f"(d[1]), "+f"(d[2]), "+f"(d[3])
        : "r"(a[0]), "r"(a[1]), "r"(a[2]), "r"(a[3]), "r"(b[0]), "r"(b[1]));
}

__device__ __forceinline__ uint32_t pack2(__nv_bfloat16 a, __nv_bfloat16 b) {
    __nv_bfloat162 v = __halves2bfloat162(a, b);
    return *reinterpret_cast<uint32_t*>(&v);
}

// ---------------------------------------------------------------------------
// fp32 projection (Q and K only; tiny: Cq=64)
// out[b][n][o] = sum_c W[o][c] * x[b][c][n] + bias[o]
// ---------------------------------------------------------------------------
__global__ void proj_kernel(const float* __restrict__ x,
                            const float* __restrict__ W,
                            const float* __restrict__ bias,
                            float* __restrict__ out, int Co) {
    const int n0 = blockIdx.x * 128;
    const int o0 = blockIdx.y * 64;
    const int b  = blockIdx.z;
    __shared__ float xs[32][128];
    __shared__ float ws[64][33];
    const int t  = threadIdx.x;
    const int ox = t & 15;
    const int ny = t >> 4;
    float acc[8][4] = {};
    const float* xb = x + (size_t)b * Cch * Np;

    for (int c0 = 0; c0 < Cch; c0 += 32) {
        #pragma unroll
        for (int r = 0; r < 16; r++) {
            int l = t + 256 * r;
            int cc = l >> 7, nn = l & 127;
            xs[cc][nn] = xb[(size_t)(c0 + cc) * Np + n0 + nn];
        }
        #pragma unroll
        for (int r = 0; r < 8; r++) {
            int l = t + 256 * r;
            int oo = l >> 5, cc = l & 31;
            ws[oo][cc] = W[(o0 + oo) * Cch + c0 + cc];
        }
        __syncthreads();
        #pragma unroll
        for (int cc = 0; cc < 32; cc++) {
            float a[8], bb[4];
            #pragma unroll
            for (int i = 0; i < 8; i++) a[i] = xs[cc][ny + 16 * i];
            #pragma unroll
            for (int j = 0; j < 4; j++) bb[j] = ws[ox + 16 * j][cc];
            #pragma unroll
            for (int i = 0; i < 8; i++)
                #pragma unroll
                for (int j = 0; j < 4; j++) acc[i][j] += a[i] * bb[j];
        }
        __syncthreads();
    }
    #pragma unroll
    for (int j = 0; j < 4; j++) {
        float bv = bias[o0 + ox + 16 * j];
        #pragma unroll
        for (int i = 0; i < 8; i++) {
            int n = n0 + ny + 16 * i;
            out[((size_t)b * Np + n) * Co + o0 + ox + 16 * j] = acc[i][j] + bv;
        }
    }
}

// ---------------------------------------------------------------------------
// V projection via tf32 MMA. Emits V^T bf16: vt[b][c][m].
//   v[c][m] = sum_k Wv[c][k] * x[b][k][m] + bv[c]
// ---------------------------------------------------------------------------
#define WS_STRIDE 36
#define XS_STRIDE 136
#define WS_BUF (128 * WS_STRIDE)
#define XS_BUF (32 * XS_STRIDE)
#define VP_SMEM ((2 * WS_BUF + 2 * XS_BUF) * 4)   // 71680 bytes

__global__ __launch_bounds__(256) void vproj_tc_kernel(
        const float* __restrict__ x,
        const float* __restrict__ W,
        const float* __restrict__ bias,
        __nv_bfloat16* __restrict__ vt) {
    const int nB = blockIdx.x * 128;
    const int cB = blockIdx.y * 128;
    const int b  = blockIdx.z;

    extern __shared__ unsigned sm[];
    unsigned* Ws = sm;
    unsigned* Xs = sm + 2 * WS_BUF;

    const int t    = threadIdx.x;
    const int wid  = t >> 5;
    const int lane = t & 31;
    const int gid  = lane >> 2;
    const int tig  = lane & 3;
    const int wc   = (wid >> 2) * 64;
    const int wn   = (wid & 3) * 32;

    const float* xb = x + (size_t)b * Cch * Np;

    float acc[4][4][4] = {};
    float4 wst[4], xst[4];

    #pragma unroll
    for (int r = 0; r < 4; r++) {
        int l4 = t + 256 * r;
        wst[r] = *(const float4*)(W + (size_t)(cB + (l4 >> 3)) * Cch + (l4 & 7) * 4);
        xst[r] = *(const float4*)(xb + (size_t)(l4 >> 5) * Np + nB + (l4 & 31) * 4);
    }
    #pragma unroll
    for (int r = 0; r < 4; r++) {
        int l4 = t + 256 * r;
        unsigned* wd = Ws + (l4 >> 3) * WS_STRIDE + (l4 & 7) * 4;
        wd[0] = f2tf32(wst[r].x); wd[1] = f2tf32(wst[r].y);
        wd[2] = f2tf32(wst[r].z); wd[3] = f2tf32(wst[r].w);
        unsigned* xd = Xs + (l4 >> 5) * XS_STRIDE + (l4 & 31) * 4;
        xd[0] = f2tf32(xst[r].x); xd[1] = f2tf32(xst[r].y);
        xd[2] = f2tf32(xst[r].z); xd[3] = f2tf32(xst[r].w);
    }
    __syncthreads();

    const int NI = Cch / 32;
    for (int it = 0; it < NI; it++) {
        const int cur = it & 1;
        if (it + 1 < NI) {
            const int c0 = (it + 1) * 32;
            #pragma unroll
            for (int r = 0; r < 4; r++) {
                int l4 = t + 256 * r;
                wst[r] = *(const float4*)(W + (size_t)(cB + (l4 >> 3)) * Cch + c0 + (l4 & 7) * 4);
                xst[r] = *(const float4*)(xb + (size_t)(c0 + (l4 >> 5)) * Np + nB + (l4 & 31) * 4);
            }
        }
        const unsigned* Wc = Ws + cur * WS_BUF;
        const unsigned* Xc = Xs + cur * XS_BUF;
        #pragma unroll
        for (int ks = 0; ks < 4; ks++) {
            const int kb = ks * 8;
            unsigned afr[4][4];
            #pragma unroll
            for (int mt = 0; mt < 4; mt++) {
                int row = wc + mt * 16 + gid;
                afr[mt][0] = Wc[row * WS_STRIDE + kb + tig];
                afr[mt][1] = Wc[(row + 8) * WS_STRIDE + kb + tig];
                afr[mt][2] = Wc[row * WS_STRIDE + kb + tig + 4];
                afr[mt][3] = Wc[(row + 8) * WS_STRIDE + kb + tig + 4];
            }
            unsigned bfr[4][2];
            #pragma unroll
            for (int nt = 0; nt < 4; nt++) {
                int col = wn + nt * 8 + gid;
                bfr[nt][0] = Xc[(kb + tig) * XS_STRIDE + col];
                bfr[nt][1] = Xc[(kb + tig + 4) * XS_STRIDE + col];
            }
            #pragma unroll
            for (int mt = 0; mt < 4; mt++)
                #pragma unroll
                for (int nt = 0; nt < 4; nt++)
                    mma_tf32(acc[mt][nt], afr[mt], bfr[nt]);
        }
        if (it + 1 < NI) {
            unsigned* Wd = Ws + (cur ^ 1) * WS_BUF;
            unsigned* Xd = Xs + (cur ^ 1) * XS_BUF;
            #pragma unroll
            for (int r = 0; r < 4; r++) {
                int l4 = t + 256 * r;
                unsigned* wd = Wd + (l4 >> 3) * WS_STRIDE + (l4 & 7) * 4;
                wd[0] = f2tf32(wst[r].x); wd[1] = f2tf32(wst[r].y);
                wd[2] = f2tf32(wst[r].z); wd[3] = f2tf32(wst[r].w);
                unsigned* xd = Xd + (l4 >> 5) * XS_STRIDE + (l4 & 31) * 4;
                xd[0] = f2tf32(xst[r].x); xd[1] = f2tf32(xst[r].y);
                xd[2] = f2tf32(xst[r].z); xd[3] = f2tf32(xst[r].w);
            }
            __syncthreads();
        }
    }

    // Epilogue: round to bf16, store V^T [c][m=n]
    __nv_bfloat16* Vb = vt + (size_t)b * Cch * Np;
    #pragma unroll
    for (int mt = 0; mt < 4; mt++) {
        int c = cB + wc + mt * 16 + gid;
        float b0 = bias[c], b1 = bias[c + 8];
        #pragma unroll
        for (int nt = 0; nt < 4; nt++) {
            int n = nB + wn + nt * 8 + 2 * tig;
            *(uint32_t*)(Vb + (size_t)c * Np + n) =
                pack2(__float2bfloat16_rn(acc[mt][nt][0] + b0),
                      __float2bfloat16_rn(acc[mt][nt][1] + b0));
            *(uint32_t*)(Vb + (size_t)(c + 8) * Np + n) =
                pack2(__float2bfloat16_rn(acc[mt][nt][2] + b1),
                      __float2bfloat16_rn(acc[mt][nt][3] + b1));
        }
    }
}

// ---------------------------------------------------------------------------
// sim via 3xTF32 split-precision MMA (fp32-equivalent accuracy)
// ---------------------------------------------------------------------------
#define QS_STRIDE 36
#define QS_BUF (128 * QS_STRIDE)
#define SIM_SMEM (4 * QS_BUF * 4)                 // 73728 bytes

__global__ __launch_bounds__(256) void sim_tc_kernel(
        const float* __restrict__ q,
        const float* __restrict__ k,
        float* __restrict__ S) {
    const int m0 = blockIdx.x * 128;
    const int n0 = blockIdx.y * 128;
    const int b  = blockIdx.z;

    extern __shared__ unsigned sm[];
    unsigned* qh = sm;
    unsigned* ql = sm + QS_BUF;
    unsigned* kh = sm + 2 * QS_BUF;
    unsigned* kl = sm + 3 * QS_BUF;

    const int t    = threadIdx.x;
    const int wid  = t >> 5;
    const int lane = t & 31;
    const int gid  = lane >> 2;
    const int tig  = lane & 3;
    const int wn   = (wid >> 2) * 64;
    const int wm   = (wid & 3) * 32;

    const float* qb = q + ((size_t)b * Np + n0) * Cqd;
    const float* kb = k + ((size_t)b * Np + m0) * Cqd;

    float acc[4][4][4] = {};

    for (int c0 = 0; c0 < Cqd; c0 += 32) {
        if (c0) __syncthreads();
        #pragma unroll
        for (int r = 0; r < 4; r++) {
            int l4 = t + 256 * r;
            int row = l4 >> 3, j4 = (l4 & 7) * 4;
            float4 vq = *(const float4*)(qb + row * Cqd + c0 + j4);
            float4 vk = *(const float4*)(kb + row * Cqd + c0 + j4);
            unsigned* qhd = qh + row * QS_STRIDE + j4;
            unsigned* qld = ql + row * QS_STRIDE + j4;
            split_tf32(vq.x, qhd[0], qld[0]); split_tf32(vq.y, qhd[1], qld[1]);
            split_tf32(vq.z, qhd[2], qld[2]); split_tf32(vq.w, qhd[3], qld[3]);
            unsigned* khd = kh + row * QS_STRIDE + j4;
            unsigned* kld = kl + row * QS_STRIDE + j4;
            split_tf32(vk.x, khd[0], kld[0]); split_tf32(vk.y, khd[1], kld[1]);
            split_tf32(vk.z, khd[2], kld[2]); split_tf32(vk.w, khd[3], kld[3]);
        }
        __syncthreads();

        #pragma unroll
        for (int ks = 0; ks < 4; ks++) {
            const int kb8 = ks * 8;
            unsigned ah[4][4], al[4][4];
            #pragma unroll
            for (int mt = 0; mt < 4; mt++) {
                int row = wn + mt * 16 + gid;
                ah[mt][0] = qh[row * QS_STRIDE + kb8 + tig];
                ah[mt][1] = qh[(row + 8) * QS_STRIDE + kb8 + tig];
                ah[mt][2] = qh[row * QS_STRIDE + kb8 + tig + 4];
                ah[mt][3] = qh[(row + 8) * QS_STRIDE + kb8 + tig + 4];
                al[mt][0] = ql[row * QS_STRIDE + kb8 + tig];
                al[mt][1] = ql[(row + 8) * QS_STRIDE + kb8 + tig];
                al[mt][2] = ql[row * QS_STRIDE + kb8 + tig + 4];
                al[mt][3] = ql[(row + 8) * QS_STRIDE + kb8 + tig + 4];
            }
            unsigned bh[4][2], bl[4][2];
            #pragma unroll
            for (int nt = 0; nt < 4; nt++) {
                int col = wm + nt * 8 + gid;
                bh[nt][0] = kh[col * QS_STRIDE + kb8 + tig];
                bh[nt][1] = kh[col * QS_STRIDE + kb8 + tig + 4];
                bl[nt][0] = kl[col * QS_STRIDE + kb8 + tig];
                bl[nt][1] = kl[col * QS_STRIDE + kb8 + tig + 4];
            }
            #pragma unroll
            for (int mt = 0; mt < 4; mt++)
                #pragma unroll
                for (int nt = 0; nt < 4; nt++) {
                    mma_tf32(acc[mt][nt], ah[mt], bl[nt]);
                    mma_tf32(acc[mt][nt], al[mt], bh[nt]);
                    mma_tf32(acc[mt][nt], ah[mt], bh[nt]);
                }
        }
    }

    float* Sb = S + ((size_t)b * Np + n0) * Np + m0;
    #pragma unroll
    for (int mt = 0; mt < 4; mt++) {
        int n = wn + mt * 16 + gid;
        #pragma unroll
        for (int nt = 0; nt < 4; nt++) {
            int m = wm + nt * 8 + 2 * tig;
            *(float2*)(Sb + (size_t)n * Np + m)       = make_float2(acc[mt][nt][0], acc[mt][nt][1]);
            *(float2*)(Sb + (size_t)(n + 8) * Np + m) = make_float2(acc[mt][nt][2], acc[mt][nt][3]);
        }
    }
}

// ---------------------------------------------------------------------------
// Row softmax: read fp32 sim, write bf16 P.
// ---------------------------------------------------------------------------
__global__ void softmax_kernel(const float* __restrict__ S,
                               __nv_bfloat16* __restrict__ P) {
    const int row = blockIdx.x;
    const int b   = blockIdx.y;
    const float* p = S + ((size_t)b * Np + row) * Np;
    __shared__ float buf[Np];
    __shared__ float red[256];
    const int t = threadIdx.x;
    const float4* p4 = (const float4*)p;
    float4* b4 = (float4*)buf;

    float lmax = -1e30f;
    #pragma unroll
    for (int r = 0; r < 4; r++) {
        float4 v = p4[t + 256 * r];
        b4[t + 256 * r] = v;
        lmax = fmaxf(lmax, fmaxf(fmaxf(v.x, v.y), fmaxf(v.z, v.w)));
    }
    red[t] = lmax;
    __syncthreads();
    for (int s = 128; s > 0; s >>= 1) {
        if (t < s) red[t] = fmaxf(red[t], red[t + s]);
        __syncthreads();
    }
    const float mx = red[0];
    __syncthreads();

    float lsum = 0.f;
    #pragma unroll
    for (int r = 0; r < 4; r++) {
        float4 v = b4[t + 256 * r];
        v.x = __expf(v.x - mx); v.y = __expf(v.y - mx);
        v.z = __expf(v.z - mx); v.w = __expf(v.w - mx);
        b4[t + 256 * r] = v;
        lsum += v.x + v.y + v.z + v.w;
    }
    red[t] = lsum;
    __syncthreads();
    for (int s = 128; s > 0; s >>= 1) {
        if (t < s) red[t] += red[t + s];
        __syncthreads();
    }
    const float inv = 1.0f / red[0];
    __syncthreads();

    uint32_t* pr = (uint32_t*)(P + ((size_t)b * Np + row) * Np);
    #pragma unroll
    for (int r = 0; r < 4; r++) {
        float4 v = b4[t + 256 * r];
        pr[(t + 256 * r) * 2]     = pack2(__float2bfloat16_rn(v.x * inv),
                                          __float2bfloat16_rn(v.y * inv));
        pr[(t + 256 * r) * 2 + 1] = pack2(__float2bfloat16_rn(v.z * inv),
                                          __float2bfloat16_rn(v.w * inv));
    }
}

// ---------------------------------------------------------------------------
// ctx via bf16 mma.sync m16n8k16 (2x tf32 rate):
//   ctx[n][c] = sum_m P[n][m] * V[m][c];  out[b][c][n] = g*ctx + x
// A = P bf16 [n][m] row-major; B = V^T bf16 [c][m] (k=m contiguous -> col-major).
// Tile 128n x 128c, k-chunk 32 m, double-buffered smem.
// Smem rows: 16 payload words (32 bf16) padded to 20 -> fragment banks
// 20*gid + tig (+4, +8) all-distinct across the warp (enumerated).
// ---------------------------------------------------------------------------
#define PS2 20
#define CT_BUF (128 * PS2)     // words per buffer per operand

__global__ __launch_bounds__(256) void ctx_bf16_kernel(
        const __nv_bfloat16* __restrict__ P,
        const __nv_bfloat16* __restrict__ Vt,
        const float* __restrict__ x,
        const float* __restrict__ gamma,
        float* __restrict__ out) {
    const int n0 = blockIdx.x * 128;
    const int c0 = blockIdx.y * 128;
    const int b  = blockIdx.z;

    __shared__ uint32_t Ps[2][CT_BUF];
    __shared__ uint32_t Vs[2][CT_BUF];

    const int t    = threadIdx.x;
    const int wid  = t >> 5;
    const int lane = t & 31;
    const int gid  = lane >> 2;
    const int tig  = lane & 3;
    const int wn   = (wid >> 2) * 64;   // n offset (0 or 64)
    const int wc   = (wid & 3) * 32;    // c offset (0..96)

    const __nv_bfloat16* Pb = P + ((size_t)b * Np + n0) * Np;     // row n, stride Np
    const __nv_bfloat16* Vb = Vt + ((size_t)b * Cch + c0) * Np;   // row c, stride Np

    float acc[4][4][4] = {};
    uint4 pst[2], vst[2];

    // load chunk 0 (128 rows x 32 bf16 = 512 16B units per operand)
    #pragma unroll
    for (int r = 0; r < 2; r++) {
        int l = t + 256 * r;
        int row = l >> 2, u = l & 3;
        pst[r] = *(const uint4*)(Pb + (size_t)row * Np + u * 8);
        vst[r] = *(const uint4*)(Vb + (size_t)row * Np + u * 8);
    }
    #pragma unroll
    for (int r = 0; r < 2; r++) {
        int l = t + 256 * r;
        int row = l >> 2, u = l & 3;
        uint32_t* pd = &Ps[0][row * PS2 + u * 4];
        pd[0] = pst[r].x; pd[1] = pst[r].y; pd[2] = pst[r].z; pd[3] = pst[r].w;
        uint32_t* vd = &Vs[0][row * PS2 + u * 4];
        vd[0] = vst[r].x; vd[1] = vst[r].y; vd[2] = vst[r].z; vd[3] = vst[r].w;
    }
    __syncthreads();

    const int NI = Np / 32;  // 128 chunks
    for (int it = 0; it < NI; it++) {
        const int cur = it & 1;
        if (it + 1 < NI) {
            const __nv_bfloat16* Pn = Pb + (it + 1) * 32;
            const __nv_bfloat16* Vn = Vb + (it + 1) * 32;
            #pragma unroll
            for (int r = 0; r < 2; r++) {
                int l = t + 256 * r;
                int row = l >> 2, u = l & 3;
                pst[r] = *(const uint4*)(Pn + (size_t)row * Np + u * 8);
                vst[r] = *(const uint4*)(Vn + (size_t)row * Np + u * 8);
            }
        }
        const uint32_t* Pc = Ps[cur];
        const uint32_t* Vc = Vs[cur];
        #pragma unroll
        for (int ks = 0; ks < 2; ks++) {        // two k16 steps per 32-chunk
            const int kb = ks * 8;
            unsigned afr[4][4];
            #pragma unroll
            for (int mt = 0; mt < 4; mt++) {
                int row = wn + mt * 16 + gid;
                afr[mt][0] = Pc[row * PS2 + kb + tig];
                afr[mt][1] = Pc[(row + 8) * PS2 + kb + tig];
                afr[mt][2] = Pc[row * PS2 + kb + tig + 4];
                afr[mt][3] = Pc[(row + 8) * PS2 + kb + tig + 4];
            }
            unsigned bfr[4][2];
            #pragma unroll
            for (int nt = 0; nt < 4; nt++) {
                int col = wc + nt * 8 + gid;
                bfr[nt][0] = Vc[col * PS2 + kb + tig];
                bfr[nt][1] = Vc[col * PS2 + kb + tig + 4];
            }
            #pragma unroll
            for (int mt = 0; mt < 4; mt++)
                #pragma unroll
                for (int nt = 0; nt < 4; nt++)
                    mma_bf16(acc[mt][nt], afr[mt], bfr[nt]);
        }
        if (it + 1 < NI) {
            uint32_t* Pd = Ps[cur ^ 1];
            uint32_t* Vd = Vs[cur ^ 1];
            #pragma unroll
            for (int r = 0; r < 2; r++) {
                int l = t + 256 * r;
                int row = l >> 2, u = l & 3;
                uint32_t* pd = &Pd[row * PS2 + u * 4];
                pd[0] = pst[r].x; pd[1] = pst[r].y; pd[2] = pst[r].z; pd[3] = pst[r].w;
                uint32_t* vd = &Vd[row * PS2 + u * 4];
                vd[0] = vst[r].x; vd[1] = vst[r].y; vd[2] = vst[r].z; vd[3] = vst[r].w;
            }
            __syncthreads();
        }
    }

    // Epilogue: out[b][c][n] = g*ctx + x
    const float g = gamma[0];
    #pragma unroll
    for (int mt = 0; mt < 4; mt++) {
        int n = n0 + wn + mt * 16 + gid;
        #pragma unroll
        for (int nt = 0; nt < 4; nt++) {
            int c = c0 + wc + nt * 8 + 2 * tig;
            size_t i00 = ((size_t)b * Cch + c) * Np + n;
            size_t i01 = ((size_t)b * Cch + c + 1) * Np + n;
            out[i00]     = g * acc[mt][nt][0] + x[i00];
            out[i01]     = g * acc[mt][nt][1] + x[i01];
            out[i00 + 8] = g * acc[mt][nt][2] + x[i00 + 8];
            out[i01 + 8] = g * acc[mt][nt][3] + x[i01 + 8];
        }
    }
}

// ---------------------------------------------------------------------------
extern "C" void kernel_launch(void* const* d_in, const int* in_sizes, int n_in,
                              void* d_out, int out_size) {
    const float* x     = (const float*)d_in[0];
    const float* Wq    = (const float*)d_in[1];
    const float* bq    = (const float*)d_in[2];
    const float* Wk    = (const float*)d_in[3];
    const float* bk    = (const float*)d_in[4];
    const float* Wv    = (const float*)d_in[5];
    const float* bv    = (const float*)d_in[6];
    const float* gamma = (const float*)d_in[7];
    float* out = (float*)d_out;

    float *q, *k, *S;
    __nv_bfloat16 *pb, *vt;
    cudaGetSymbolAddress((void**)&q, g_q);
    cudaGetSymbolAddress((void**)&k, g_k);
    cudaGetSymbolAddress((void**)&S, g_s);
    cudaGetSymbolAddress((void**)&pb, g_pb);
    cudaGetSymbolAddress((void**)&vt, g_vt);

    static int smem_set = 0;
    if (!smem_set) {
        cudaFuncSetAttribute(vproj_tc_kernel,
                             cudaFuncAttributeMaxDynamicSharedMemorySize, VP_SMEM);
        cudaFuncSetAttribute(sim_tc_kernel,
                             cudaFuncAttributeMaxDynamicSharedMemorySize, SIM_SMEM);
        smem_set = 1;
    }

    dim3 thr(256);
    proj_kernel<<<dim3(Np / 128, 1, Bsz), thr>>>(x, Wq, bq, q, Cqd);
    proj_kernel<<<dim3(Np / 128, 1, Bsz), thr>>>(x, Wk, bk, k, Cqd);
    vproj_tc_kernel<<<dim3(Np / 128, Cch / 128, Bsz), thr, VP_SMEM>>>(x, Wv, bv, vt);
    sim_tc_kernel<<<dim3(Np / 128, Np / 128, Bsz), thr, SIM_SMEM>>>(q, k, S);
    softmax_kernel<<<dim3(Np, Bsz), thr>>>(S, pb);
    ctx_bf16_kernel<<<dim3(Np / 128, Cch / 128, Bsz), thr>>>(pb, vt, x, gamma, out);
}

// round 12
// speedup vs baseline: 5.0574x; 1.0972x over previous
#include <cuda_runtime.h>
#include <cuda_bf16.h>
#include <cstdint>

// Problem constants
#define Bsz 4
#define Cch 512
#define Np  4096     // H*W = 64*64
#define Cqd 64

// Scratch (device globals; allocation-free per harness rules)
__device__ float g_q[Bsz * Np * Cqd];                       // [B][N][Cq]   4 MB
__device__ float g_k[Bsz * Np * Cqd];                       // [B][N][Cq]   4 MB
__device__ float g_rowsum[Bsz * Np];                        // exp row sums 64 KB
__device__ __nv_bfloat16 g_pb[(size_t)Bsz * Np * Np];       // exp(sim) bf16 128 MB
__device__ __nv_bfloat16 g_vt[(size_t)Bsz * Cch * Np];      // V^T bf16    16 MB

#define EXP_OFF 32.0f   // fixed logit shift: neutral in softmax ratio, overflow guard

// ---------------------------------------------------------------------------
// Helpers
// ---------------------------------------------------------------------------
__device__ __forceinline__ unsigned f2tf32(float f) {
    unsigned u;
    asm("cvt.rna.tf32.f32 %0, %1;" : "=r"(u) : "f"(f));
    return u;
}

__device__ __forceinline__ void split_tf32(float v, unsigned& hi, unsigned& lo) {
    unsigned h = f2tf32(v);
    hi = h;
    lo = f2tf32(v - __uint_as_float(h));
}

__device__ __forceinline__ void mma_tf32(float* d, const unsigned* a, const unsigned* b) {
    asm volatile(
        "mma.sync.aligned.m16n8k8.row.col.f32.tf32.tf32.f32 "
        "{%0,%1,%2,%3}, {%4,%5,%6,%7}, {%8,%9}, {%0,%1,%2,%3};\n"
        : "+f"(d[0]), "+f"(d[1]), "+f"(d[2]), "+f"(d[3])
        : "r"(a[0]), "r"(a[1]), "r"(a[2]), "r"(a[3]), "r"(b[0]), "r"(b[1]));
}

__device__ __forceinline__ void mma_bf16(float* d, const unsigned* a, const unsigned* b) {
    asm volatile(
        "mma.sync.aligned.m16n8k16.row.col.f32.bf16.bf16.f32 "
        "{%0,%1,%2,%3}, {%4,%5,%6,%7}, {%8,%9}, {%0,%1,%2,%3};\n"
        : "+f"(d[0]), "+f"(d[1]), "+f"(d[2]), "+f"(d[3])
        : "r"(a[0]), "r"(a[1]), "r"(a[2]), "r"(a[3]), "r"(b[0]), "r"(b[1]));
}

__device__ __forceinline__ uint32_t pack2(__nv_bfloat16 a, __nv_bfloat16 b) {
    __nv_bfloat162 v = __halves2bfloat162(a, b);
    return *reinterpret_cast<uint32_t*>(&v);
}

// ---------------------------------------------------------------------------
// Zero the rowsum accumulator (replaces cudaMemsetAsync: keeps the captured
// graph kernel-launch-only, matching the harness whitelist).
// ---------------------------------------------------------------------------
__global__ void zero_rowsum_kernel(float* __restrict__ rs) {
    rs[blockIdx.x * 256 + threadIdx.x] = 0.0f;
}

// ---------------------------------------------------------------------------
// fp32 projection (Q and K only; tiny: Cq=64)
// out[b][n][o] = sum_c W[o][c] * x[b][c][n] + bias[o]
// ---------------------------------------------------------------------------
__global__ void proj_kernel(const float* __restrict__ x,
                            const float* __restrict__ W,
                            const float* __restrict__ bias,
                            float* __restrict__ out, int Co) {
    const int n0 = blockIdx.x * 128;
    const int o0 = blockIdx.y * 64;
    const int b  = blockIdx.z;
    __shared__ float xs[32][128];
    __shared__ float ws[64][33];
    const int t  = threadIdx.x;
    const int ox = t & 15;
    const int ny = t >> 4;
    float acc[8][4] = {};
    const float* xb = x + (size_t)b * Cch * Np;

    for (int c0 = 0; c0 < Cch; c0 += 32) {
        #pragma unroll
        for (int r = 0; r < 16; r++) {
            int l = t + 256 * r;
            int cc = l >> 7, nn = l & 127;
            xs[cc][nn] = xb[(size_t)(c0 + cc) * Np + n0 + nn];
        }
        #pragma unroll
        for (int r = 0; r < 8; r++) {
            int l = t + 256 * r;
            int oo = l >> 5, cc = l & 31;
            ws[oo][cc] = W[(o0 + oo) * Cch + c0 + cc];
        }
        __syncthreads();
        #pragma unroll
        for (int cc = 0; cc < 32; cc++) {
            float a[8], bb[4];
            #pragma unroll
            for (int i = 0; i < 8; i++) a[i] = xs[cc][ny + 16 * i];
            #pragma unroll
            for (int j = 0; j < 4; j++) bb[j] = ws[ox + 16 * j][cc];
            #pragma unroll
            for (int i = 0; i < 8; i++)
                #pragma unroll
                for (int j = 0; j < 4; j++) acc[i][j] += a[i] * bb[j];
        }
        __syncthreads();
    }
    #pragma unroll
    for (int j = 0; j < 4; j++) {
        float bv = bias[o0 + ox + 16 * j];
        #pragma unroll
        for (int i = 0; i < 8; i++) {
            int n = n0 + ny + 16 * i;
            out[((size_t)b * Np + n) * Co + o0 + ox + 16 * j] = acc[i][j] + bv;
        }
    }
}

// ---------------------------------------------------------------------------
// V projection via tf32 MMA. Emits V^T bf16: vt[b][c][m].
//   v[c][m] = sum_k Wv[c][k] * x[b][k][m] + bv[c]
// ---------------------------------------------------------------------------
#define WS_STRIDE 36
#define XS_STRIDE 136
#define WS_BUF (128 * WS_STRIDE)
#define XS_BUF (32 * XS_STRIDE)
#define VP_SMEM ((2 * WS_BUF + 2 * XS_BUF) * 4)   // 71680 bytes

__global__ __launch_bounds__(256) void vproj_tc_kernel(
        const float* __restrict__ x,
        const float* __restrict__ W,
        const float* __restrict__ bias,
        __nv_bfloat16* __restrict__ vt) {
    const int nB = blockIdx.x * 128;
    const int cB = blockIdx.y * 128;
    const int b  = blockIdx.z;

    extern __shared__ unsigned sm[];
    unsigned* Ws = sm;
    unsigned* Xs = sm + 2 * WS_BUF;

    const int t    = threadIdx.x;
    const int wid  = t >> 5;
    const int lane = t & 31;
    const int gid  = lane >> 2;
    const int tig  = lane & 3;
    const int wc   = (wid >> 2) * 64;
    const int wn   = (wid & 3) * 32;

    const float* xb = x + (size_t)b * Cch * Np;

    float acc[4][4][4] = {};
    float4 wst[4], xst[4];

    #pragma unroll
    for (int r = 0; r < 4; r++) {
        int l4 = t + 256 * r;
        wst[r] = *(const float4*)(W + (size_t)(cB + (l4 >> 3)) * Cch + (l4 & 7) * 4);
        xst[r] = *(const float4*)(xb + (size_t)(l4 >> 5) * Np + nB + (l4 & 31) * 4);
    }
    #pragma unroll
    for (int r = 0; r < 4; r++) {
        int l4 = t + 256 * r;
        unsigned* wd = Ws + (l4 >> 3) * WS_STRIDE + (l4 & 7) * 4;
        wd[0] = f2tf32(wst[r].x); wd[1] = f2tf32(wst[r].y);
        wd[2] = f2tf32(wst[r].z); wd[3] = f2tf32(wst[r].w);
        unsigned* xd = Xs + (l4 >> 5) * XS_STRIDE + (l4 & 31) * 4;
        xd[0] = f2tf32(xst[r].x); xd[1] = f2tf32(xst[r].y);
        xd[2] = f2tf32(xst[r].z); xd[3] = f2tf32(xst[r].w);
    }
    __syncthreads();

    const int NI = Cch / 32;
    for (int it = 0; it < NI; it++) {
        const int cur = it & 1;
        if (it + 1 < NI) {
            const int c0 = (it + 1) * 32;
            #pragma unroll
            for (int r = 0; r < 4; r++) {
                int l4 = t + 256 * r;
                wst[r] = *(const float4*)(W + (size_t)(cB + (l4 >> 3)) * Cch + c0 + (l4 & 7) * 4);
                xst[r] = *(const float4*)(xb + (size_t)(c0 + (l4 >> 5)) * Np + nB + (l4 & 31) * 4);
            }
        }
        const unsigned* Wc = Ws + cur * WS_BUF;
        const unsigned* Xc = Xs + cur * XS_BUF;
        #pragma unroll
        for (int ks = 0; ks < 4; ks++) {
            const int kb = ks * 8;
            unsigned afr[4][4];
            #pragma unroll
            for (int mt = 0; mt < 4; mt++) {
                int row = wc + mt * 16 + gid;
                afr[mt][0] = Wc[row * WS_STRIDE + kb + tig];
                afr[mt][1] = Wc[(row + 8) * WS_STRIDE + kb + tig];
                afr[mt][2] = Wc[row * WS_STRIDE + kb + tig + 4];
                afr[mt][3] = Wc[(row + 8) * WS_STRIDE + kb + tig + 4];
            }
            unsigned bfr[4][2];
            #pragma unroll
            for (int nt = 0; nt < 4; nt++) {
                int col = wn + nt * 8 + gid;
                bfr[nt][0] = Xc[(kb + tig) * XS_STRIDE + col];
                bfr[nt][1] = Xc[(kb + tig + 4) * XS_STRIDE + col];
            }
            #pragma unroll
            for (int mt = 0; mt < 4; mt++)
                #pragma unroll
                for (int nt = 0; nt < 4; nt++)
                    mma_tf32(acc[mt][nt], afr[mt], bfr[nt]);
        }
        if (it + 1 < NI) {
            unsigned* Wd = Ws + (cur ^ 1) * WS_BUF;
            unsigned* Xd = Xs + (cur ^ 1) * XS_BUF;
            #pragma unroll
            for (int r = 0; r < 4; r++) {
                int l4 = t + 256 * r;
                unsigned* wd = Wd + (l4 >> 3) * WS_STRIDE + (l4 & 7) * 4;
                wd[0] = f2tf32(wst[r].x); wd[1] = f2tf32(wst[r].y);
                wd[2] = f2tf32(wst[r].z); wd[3] = f2tf32(wst[r].w);
                unsigned* xd = Xd + (l4 >> 5) * XS_STRIDE + (l4 & 31) * 4;
                xd[0] = f2tf32(xst[r].x); xd[1] = f2tf32(xst[r].y);
                xd[2] = f2tf32(xst[r].z); xd[3] = f2tf32(xst[r].w);
            }
            __syncthreads();
        }
    }

    // Epilogue: round to bf16, store V^T [c][m=n]
    __nv_bfloat16* Vb = vt + (size_t)b * Cch * Np;
    #pragma unroll
    for (int mt = 0; mt < 4; mt++) {
        int c = cB + wc + mt * 16 + gid;
        float b0 = bias[c], b1 = bias[c + 8];
        #pragma unroll
        for (int nt = 0; nt < 4; nt++) {
            int n = nB + wn + nt * 8 + 2 * tig;
            *(uint32_t*)(Vb + (size_t)c * Np + n) =
                pack2(__float2bfloat16_rn(acc[mt][nt][0] + b0),
                      __float2bfloat16_rn(acc[mt][nt][1] + b0));
            *(uint32_t*)(Vb + (size_t)(c + 8) * Np + n) =
                pack2(__float2bfloat16_rn(acc[mt][nt][2] + b1),
                      __float2bfloat16_rn(acc[mt][nt][3] + b1));
        }
    }
}

// ---------------------------------------------------------------------------
// sim via 3xTF32 split-precision MMA, FUSED exp epilogue:
//   e[n][m] = exp(q.k - EXP_OFF)  -> bf16 P;  rowsum[n] += partial sums.
// Normalization is deferred to ctx (divide by rowsum) — exact softmax ratio.
// ---------------------------------------------------------------------------
#define QS_STRIDE 36
#define QS_BUF (128 * QS_STRIDE)
#define SIM_SMEM (4 * QS_BUF * 4)                 // 73728 bytes

__global__ __launch_bounds__(256) void sim_tc_kernel(
        const float* __restrict__ q,
        const float* __restrict__ k,
        __nv_bfloat16* __restrict__ P,
        float* __restrict__ rowsum) {
    const int m0 = blockIdx.x * 128;
    const int n0 = blockIdx.y * 128;
    const int b  = blockIdx.z;

    extern __shared__ unsigned sm[];
    unsigned* qh = sm;
    unsigned* ql = sm + QS_BUF;
    unsigned* kh = sm + 2 * QS_BUF;
    unsigned* kl = sm + 3 * QS_BUF;

    const int t    = threadIdx.x;
    const int wid  = t >> 5;
    const int lane = t & 31;
    const int gid  = lane >> 2;
    const int tig  = lane & 3;
    const int wn   = (wid >> 2) * 64;
    const int wm   = (wid & 3) * 32;

    const float* qb = q + ((size_t)b * Np + n0) * Cqd;
    const float* kb = k + ((size_t)b * Np + m0) * Cqd;

    float acc[4][4][4] = {};

    for (int c0 = 0; c0 < Cqd; c0 += 32) {
        if (c0) __syncthreads();
        #pragma unroll
        for (int r = 0; r < 4; r++) {
            int l4 = t + 256 * r;
            int row = l4 >> 3, j4 = (l4 & 7) * 4;
            float4 vq = *(const float4*)(qb + row * Cqd + c0 + j4);
            float4 vk = *(const float4*)(kb + row * Cqd + c0 + j4);
            unsigned* qhd = qh + row * QS_STRIDE + j4;
            unsigned* qld = ql + row * QS_STRIDE + j4;
            split_tf32(vq.x, qhd[0], qld[0]); split_tf32(vq.y, qhd[1], qld[1]);
            split_tf32(vq.z, qhd[2], qld[2]); split_tf32(vq.w, qhd[3], qld[3]);
            unsigned* khd = kh + row * QS_STRIDE + j4;
            unsigned* kld = kl + row * QS_STRIDE + j4;
            split_tf32(vk.x, khd[0], kld[0]); split_tf32(vk.y, khd[1], kld[1]);
            split_tf32(vk.z, khd[2], kld[2]); split_tf32(vk.w, khd[3], kld[3]);
        }
        __syncthreads();

        #pragma unroll
        for (int ks = 0; ks < 4; ks++) {
            const int kb8 = ks * 8;
            unsigned ah[4][4], al[4][4];
            #pragma unroll
            for (int mt = 0; mt < 4; mt++) {
                int row = wn + mt * 16 + gid;
                ah[mt][0] = qh[row * QS_STRIDE + kb8 + tig];
                ah[mt][1] = qh[(row + 8) * QS_STRIDE + kb8 + tig];
                ah[mt][2] = qh[row * QS_STRIDE + kb8 + tig + 4];
                ah[mt][3] = qh[(row + 8) * QS_STRIDE + kb8 + tig + 4];
                al[mt][0] = ql[row * QS_STRIDE + kb8 + tig];
                al[mt][1] = ql[(row + 8) * QS_STRIDE + kb8 + tig];
                al[mt][2] = ql[row * QS_STRIDE + kb8 + tig + 4];
                al[mt][3] = ql[(row + 8) * QS_STRIDE + kb8 + tig + 4];
            }
            unsigned bh[4][2], bl[4][2];
            #pragma unroll
            for (int nt = 0; nt < 4; nt++) {
                int col = wm + nt * 8 + gid;
                bh[nt][0] = kh[col * QS_STRIDE + kb8 + tig];
                bh[nt][1] = kh[col * QS_STRIDE + kb8 + tig + 4];
                bl[nt][0] = kl[col * QS_STRIDE + kb8 + tig];
                bl[nt][1] = kl[col * QS_STRIDE + kb8 + tig + 4];
            }
            #pragma unroll
            for (int mt = 0; mt < 4; mt++)
                #pragma unroll
                for (int nt = 0; nt < 4; nt++) {
                    mma_tf32(acc[mt][nt], ah[mt], bl[nt]);
                    mma_tf32(acc[mt][nt], al[mt], bh[nt]);
                    mma_tf32(acc[mt][nt], ah[mt], bh[nt]);
                }
        }
    }

    // Fused exp epilogue
    #pragma unroll
    for (int mt = 0; mt < 4; mt++)
        #pragma unroll
        for (int nt = 0; nt < 4; nt++)
            #pragma unroll
            for (int v = 0; v < 4; v++)
                acc[mt][nt][v] = __expf(acc[mt][nt][v] - EXP_OFF);

    __nv_bfloat16* Pb = P + ((size_t)b * Np + n0) * Np + m0;
    #pragma unroll
    for (int mt = 0; mt < 4; mt++) {
        int n = wn + mt * 16 + gid;
        #pragma unroll
        for (int nt = 0; nt < 4; nt++) {
            int m = wm + nt * 8 + 2 * tig;
            *(uint32_t*)(Pb + (size_t)n * Np + m) =
                pack2(__float2bfloat16_rn(acc[mt][nt][0]),
                      __float2bfloat16_rn(acc[mt][nt][1]));
            *(uint32_t*)(Pb + (size_t)(n + 8) * Np + m) =
                pack2(__float2bfloat16_rn(acc[mt][nt][2]),
                      __float2bfloat16_rn(acc[mt][nt][3]));
        }
    }

    // Row partial sums: reduce over this thread's 8 m-values, then over the
    // quad (tig 0-3 share the same rows), then atomicAdd (spread addresses).
    float* rs = rowsum + (size_t)b * Np + n0;
    #pragma unroll
    for (int mt = 0; mt < 4; mt++) {
        float s0 = 0.f, s1 = 0.f;
        #pragma unroll
        for (int nt = 0; nt < 4; nt++) {
            s0 += acc[mt][nt][0] + acc[mt][nt][1];
            s1 += acc[mt][nt][2] + acc[mt][nt][3];
        }
        s0 += __shfl_xor_sync(0xFFFFFFFF, s0, 1);
        s0 += __shfl_xor_sync(0xFFFFFFFF, s0, 2);
        s1 += __shfl_xor_sync(0xFFFFFFFF, s1, 1);
        s1 += __shfl_xor_sync(0xFFFFFFFF, s1, 2);
        if (tig == 0) {
            int n = wn + mt * 16 + gid;
            atomicAdd(rs + n, s0);
            atomicAdd(rs + n + 8, s1);
        }
    }
}

// ---------------------------------------------------------------------------
// ctx via bf16 mma.sync m16n8k16; epilogue divides by rowsum:
//   out[b][c][n] = g * (sum_m e[n][m]*V[m][c]) / rowsum[n] + x
// ---------------------------------------------------------------------------
#define PS2 20
#define CT_BUF (128 * PS2)

__global__ __launch_bounds__(256) void ctx_bf16_kernel(
        const __nv_bfloat16* __restrict__ P,
        const __nv_bfloat16* __restrict__ Vt,
        const float* __restrict__ rowsum,
        const float* __restrict__ x,
        const float* __restrict__ gamma,
        float* __restrict__ out) {
    const int n0 = blockIdx.x * 128;
    const int c0 = blockIdx.y * 128;
    const int b  = blockIdx.z;

    __shared__ uint32_t Ps[2][CT_BUF];
    __shared__ uint32_t Vs[2][CT_BUF];

    const int t    = threadIdx.x;
    const int wid  = t >> 5;
    const int lane = t & 31;
    const int gid  = lane >> 2;
    const int tig  = lane & 3;
    const int wn   = (wid >> 2) * 64;
    const int wc   = (wid & 3) * 32;

    const __nv_bfloat16* Pb = P + ((size_t)b * Np + n0) * Np;
    const __nv_bfloat16* Vb = Vt + ((size_t)b * Cch + c0) * Np;

    float acc[4][4][4] = {};
    uint4 pst[2], vst[2];

    #pragma unroll
    for (int r = 0; r < 2; r++) {
        int l = t + 256 * r;
        int row = l >> 2, u = l & 3;
        pst[r] = *(const uint4*)(Pb + (size_t)row * Np + u * 8);
        vst[r] = *(const uint4*)(Vb + (size_t)row * Np + u * 8);
    }
    #pragma unroll
    for (int r = 0; r < 2; r++) {
        int l = t + 256 * r;
        int row = l >> 2, u = l & 3;
        uint32_t* pd = &Ps[0][row * PS2 + u * 4];
        pd[0] = pst[r].x; pd[1] = pst[r].y; pd[2] = pst[r].z; pd[3] = pst[r].w;
        uint32_t* vd = &Vs[0][row * PS2 + u * 4];
        vd[0] = vst[r].x; vd[1] = vst[r].y; vd[2] = vst[r].z; vd[3] = vst[r].w;
    }
    __syncthreads();

    const int NI = Np / 32;
    for (int it = 0; it < NI; it++) {
        const int cur = it & 1;
        if (it + 1 < NI) {
            const __nv_bfloat16* Pn = Pb + (it + 1) * 32;
            const __nv_bfloat16* Vn = Vb + (it + 1) * 32;
            #pragma unroll
            for (int r = 0; r < 2; r++) {
                int l = t + 256 * r;
                int row = l >> 2, u = l & 3;
                pst[r] = *(const uint4*)(Pn + (size_t)row * Np + u * 8);
                vst[r] = *(const uint4*)(Vn + (size_t)row * Np + u * 8);
            }
        }
        const uint32_t* Pc = Ps[cur];
        const uint32_t* Vc = Vs[cur];
        #pragma unroll
        for (int ks = 0; ks < 2; ks++) {
            const int kb = ks * 8;
            unsigned afr[4][4];
            #pragma unroll
            for (int mt = 0; mt < 4; mt++) {
                int row = wn + mt * 16 + gid;
                afr[mt][0] = Pc[row * PS2 + kb + tig];
                afr[mt][1] = Pc[(row + 8) * PS2 + kb + tig];
                afr[mt][2] = Pc[row * PS2 + kb + tig + 4];
                afr[mt][3] = Pc[(row + 8) * PS2 + kb + tig + 4];
            }
            unsigned bfr[4][2];
            #pragma unroll
            for (int nt = 0; nt < 4; nt++) {
                int col = wc + nt * 8 + gid;
                bfr[nt][0] = Vc[col * PS2 + kb + tig];
                bfr[nt][1] = Vc[col * PS2 + kb + tig + 4];
            }
            #pragma unroll
            for (int mt = 0; mt < 4; mt++)
                #pragma unroll
                for (int nt = 0; nt < 4; nt++)
                    mma_bf16(acc[mt][nt], afr[mt], bfr[nt]);
        }
        if (it + 1 < NI) {
            uint32_t* Pd = Ps[cur ^ 1];
            uint32_t* Vd = Vs[cur ^ 1];
            #pragma unroll
            for (int r = 0; r < 2; r++) {
                int l = t + 256 * r;
                int row = l >> 2, u = l & 3;
                uint32_t* pd = &Pd[row * PS2 + u * 4];
                pd[0] = pst[r].x; pd[1] = pst[r].y; pd[2] = pst[r].z; pd[3] = pst[r].w;
                uint32_t* vd = &Vd[row * PS2 + u * 4];
                vd[0] = vst[r].x; vd[1] = vst[r].y; vd[2] = vst[r].z; vd[3] = vst[r].w;
            }
            __syncthreads();
        }
    }

    // Epilogue: out[b][c][n] = g * acc / rowsum[n] + x
    const float g = gamma[0];
    const float* rs = rowsum + (size_t)b * Np + n0;
    #pragma unroll
    for (int mt = 0; mt < 4; mt++) {
        int n = n0 + wn + mt * 16 + gid;
        float inv0 = g / rs[wn + mt * 16 + gid];
        float inv1 = g / rs[wn + mt * 16 + gid + 8];
        #pragma unroll
        for (int nt = 0; nt < 4; nt++) {
            int c = c0 + wc + nt * 8 + 2 * tig;
            size_t i00 = ((size_t)b * Cch + c) * Np + n;
            size_t i01 = ((size_t)b * Cch + c + 1) * Np + n;
            out[i00]     = inv0 * acc[mt][nt][0] + x[i00];
            out[i01]     = inv0 * acc[mt][nt][1] + x[i01];
            out[i00 + 8] = inv1 * acc[mt][nt][2] + x[i00 + 8];
            out[i01 + 8] = inv1 * acc[mt][nt][3] + x[i01 + 8];
        }
    }
}

// ---------------------------------------------------------------------------
extern "C" void kernel_launch(void* const* d_in, const int* in_sizes, int n_in,
                              void* d_out, int out_size) {
    const float* x     = (const float*)d_in[0];
    const float* Wq    = (const float*)d_in[1];
    const float* bq    = (const float*)d_in[2];
    const float* Wk    = (const float*)d_in[3];
    const float* bk    = (const float*)d_in[4];
    const float* Wv    = (const float*)d_in[5];
    const float* bv    = (const float*)d_in[6];
    const float* gamma = (const float*)d_in[7];
    float* out = (float*)d_out;

    float *q, *k, *rsum;
    __nv_bfloat16 *pb, *vt;
    cudaGetSymbolAddress((void**)&q, g_q);
    cudaGetSymbolAddress((void**)&k, g_k);
    cudaGetSymbolAddress((void**)&rsum, g_rowsum);
    cudaGetSymbolAddress((void**)&pb, g_pb);
    cudaGetSymbolAddress((void**)&vt, g_vt);

    static int smem_set = 0;
    if (!smem_set) {
        cudaFuncSetAttribute(vproj_tc_kernel,
                             cudaFuncAttributeMaxDynamicSharedMemorySize, VP_SMEM);
        cudaFuncSetAttribute(sim_tc_kernel,
                             cudaFuncAttributeMaxDynamicSharedMemorySize, SIM_SMEM);
        smem_set = 1;
    }

    dim3 thr(256);
    zero_rowsum_kernel<<<Bsz * Np / 256, thr>>>(rsum);
    proj_kernel<<<dim3(Np / 128, 1, Bsz), thr>>>(x, Wq, bq, q, Cqd);
    proj_kernel<<<dim3(Np / 128, 1, Bsz), thr>>>(x, Wk, bk, k, Cqd);
    vproj_tc_kernel<<<dim3(Np / 128, Cch / 128, Bsz), thr, VP_SMEM>>>(x, Wv, bv, vt);
    sim_tc_kernel<<<dim3(Np / 128, Np / 128, Bsz), thr, SIM_SMEM>>>(q, k, pb, rsum);
    ctx_bf16_kernel<<<dim3(Np / 128, Cch / 128, Bsz), thr>>>(pb, vt, rsum, x, gamma, out);
}

// round 13
// speedup vs baseline: 5.4721x; 1.0820x over previous
#include <cuda_runtime.h>
#include <cuda_bf16.h>
#include <cstdint>

// Problem constants
#define Bsz 4
#define Cch 512
#define Np  4096     // H*W = 64*64
#define Cqd 64

// Scratch (device globals; allocation-free per harness rules)
__device__ float g_q[Bsz * Np * Cqd];                       // [B][N][Cq]   4 MB
__device__ float g_k[Bsz * Np * Cqd];                       // [B][N][Cq]   4 MB
__device__ float g_rowsum[Bsz * Np];                        // exp row sums 64 KB
__device__ __nv_bfloat16 g_pb[(size_t)Bsz * Np * Np];       // exp(sim) bf16 128 MB
__device__ __nv_bfloat16 g_vt[(size_t)Bsz * Cch * Np];      // V^T bf16    16 MB

#define EXP_OFF 32.0f   // fixed logit shift: neutral in softmax ratio, overflow guard

// ---------------------------------------------------------------------------
// Helpers
// ---------------------------------------------------------------------------
__device__ __forceinline__ unsigned f2tf32(float f) {
    unsigned u;
    asm("cvt.rna.tf32.f32 %0, %1;" : "=r"(u) : "f"(f));
    return u;
}

__device__ __forceinline__ void mma_tf32(float* d, const unsigned* a, const unsigned* b) {
    asm volatile(
        "mma.sync.aligned.m16n8k8.row.col.f32.tf32.tf32.f32 "
        "{%0,%1,%2,%3}, {%4,%5,%6,%7}, {%8,%9}, {%0,%1,%2,%3};\n"
        : "+f"(d[0]), "+f"(d[1]), "+f"(d[2]), "+f"(d[3])
        : "r"(a[0]), "r"(a[1]), "r"(a[2]), "r"(a[3]), "r"(b[0]), "r"(b[1]));
}

__device__ __forceinline__ void mma_bf16(float* d, const unsigned* a, const unsigned* b) {
    asm volatile(
        "mma.sync.aligned.m16n8k16.row.col.f32.bf16.bf16.f32 "
        "{%0,%1,%2,%3}, {%4,%5,%6,%7}, {%8,%9}, {%0,%1,%2,%3};\n"
        : "+f"(d[0]), "+f"(d[1]), "+f"(d[2]), "+f"(d[3])
        : "r"(a[0]), "r"(a[1]), "r"(a[2]), "r"(a[3]), "r"(b[0]), "r"(b[1]));
}

__device__ __forceinline__ uint32_t pack2(__nv_bfloat16 a, __nv_bfloat16 b) {
    __nv_bfloat162 v = __halves2bfloat162(a, b);
    return *reinterpret_cast<uint32_t*>(&v);
}

__device__ __forceinline__ void split_bf16(float v, __nv_bfloat16& h, __nv_bfloat16& l) {
    h = __float2bfloat16_rn(v);
    l = __float2bfloat16_rn(v - __bfloat162float(h));
}

// ---------------------------------------------------------------------------
// Zero the rowsum accumulator (kernel-launch-only graph; no memset nodes).
// ---------------------------------------------------------------------------
__global__ void zero_rowsum_kernel(float* __restrict__ rs) {
    rs[blockIdx.x * 256 + threadIdx.x] = 0.0f;
}

// ---------------------------------------------------------------------------
// fp32 projection (Q and K only; tiny: Cq=64)
// out[b][n][o] = sum_c W[o][c] * x[b][c][n] + bias[o]
// ---------------------------------------------------------------------------
__global__ void proj_kernel(const float* __restrict__ x,
                            const float* __restrict__ W,
                            const float* __restrict__ bias,
                            float* __restrict__ out, int Co) {
    const int n0 = blockIdx.x * 128;
    const int o0 = blockIdx.y * 64;
    const int b  = blockIdx.z;
    __shared__ float xs[32][128];
    __shared__ float ws[64][33];
    const int t  = threadIdx.x;
    const int ox = t & 15;
    const int ny = t >> 4;
    float acc[8][4] = {};
    const float* xb = x + (size_t)b * Cch * Np;

    for (int c0 = 0; c0 < Cch; c0 += 32) {
        #pragma unroll
        for (int r = 0; r < 16; r++) {
            int l = t + 256 * r;
            int cc = l >> 7, nn = l & 127;
            xs[cc][nn] = xb[(size_t)(c0 + cc) * Np + n0 + nn];
        }
        #pragma unroll
        for (int r = 0; r < 8; r++) {
            int l = t + 256 * r;
            int oo = l >> 5, cc = l & 31;
            ws[oo][cc] = W[(o0 + oo) * Cch + c0 + cc];
        }
        __syncthreads();
        #pragma unroll
        for (int cc = 0; cc < 32; cc++) {
            float a[8], bb[4];
            #pragma unroll
            for (int i = 0; i < 8; i++) a[i] = xs[cc][ny + 16 * i];
            #pragma unroll
            for (int j = 0; j < 4; j++) bb[j] = ws[ox + 16 * j][cc];
            #pragma unroll
            for (int i = 0; i < 8; i++)
                #pragma unroll
                for (int j = 0; j < 4; j++) acc[i][j] += a[i] * bb[j];
        }
        __syncthreads();
    }
    #pragma unroll
    for (int j = 0; j < 4; j++) {
        float bv = bias[o0 + ox + 16 * j];
        #pragma unroll
        for (int i = 0; i < 8; i++) {
            int n = n0 + ny + 16 * i;
            out[((size_t)b * Np + n) * Co + o0 + ox + 16 * j] = acc[i][j] + bv;
        }
    }
}

// ---------------------------------------------------------------------------
// V projection via tf32 MMA. Emits V^T bf16: vt[b][c][m].
//   v[c][m] = sum_k Wv[c][k] * x[b][k][m] + bv[c]
// ---------------------------------------------------------------------------
#define WS_STRIDE 36
#define XS_STRIDE 136
#define WS_BUF (128 * WS_STRIDE)
#define XS_BUF (32 * XS_STRIDE)
#define VP_SMEM ((2 * WS_BUF + 2 * XS_BUF) * 4)   // 71680 bytes

__global__ __launch_bounds__(256) void vproj_tc_kernel(
        const float* __restrict__ x,
        const float* __restrict__ W,
        const float* __restrict__ bias,
        __nv_bfloat16* __restrict__ vt) {
    const int nB = blockIdx.x * 128;
    const int cB = blockIdx.y * 128;
    const int b  = blockIdx.z;

    extern __shared__ unsigned sm[];
    unsigned* Ws = sm;
    unsigned* Xs = sm + 2 * WS_BUF;

    const int t    = threadIdx.x;
    const int wid  = t >> 5;
    const int lane = t & 31;
    const int gid  = lane >> 2;
    const int tig  = lane & 3;
    const int wc   = (wid >> 2) * 64;
    const int wn   = (wid & 3) * 32;

    const float* xb = x + (size_t)b * Cch * Np;

    float acc[4][4][4] = {};
    float4 wst[4], xst[4];

    #pragma unroll
    for (int r = 0; r < 4; r++) {
        int l4 = t + 256 * r;
        wst[r] = *(const float4*)(W + (size_t)(cB + (l4 >> 3)) * Cch + (l4 & 7) * 4);
        xst[r] = *(const float4*)(xb + (size_t)(l4 >> 5) * Np + nB + (l4 & 31) * 4);
    }
    #pragma unroll
    for (int r = 0; r < 4; r++) {
        int l4 = t + 256 * r;
        unsigned* wd = Ws + (l4 >> 3) * WS_STRIDE + (l4 & 7) * 4;
        wd[0] = f2tf32(wst[r].x); wd[1] = f2tf32(wst[r].y);
        wd[2] = f2tf32(wst[r].z); wd[3] = f2tf32(wst[r].w);
        unsigned* xd = Xs + (l4 >> 5) * XS_STRIDE + (l4 & 31) * 4;
        xd[0] = f2tf32(xst[r].x); xd[1] = f2tf32(xst[r].y);
        xd[2] = f2tf32(xst[r].z); xd[3] = f2tf32(xst[r].w);
    }
    __syncthreads();

    const int NI = Cch / 32;
    for (int it = 0; it < NI; it++) {
        const int cur = it & 1;
        if (it + 1 < NI) {
            const int c0 = (it + 1) * 32;
            #pragma unroll
            for (int r = 0; r < 4; r++) {
                int l4 = t + 256 * r;
                wst[r] = *(const float4*)(W + (size_t)(cB + (l4 >> 3)) * Cch + c0 + (l4 & 7) * 4);
                xst[r] = *(const float4*)(xb + (size_t)(c0 + (l4 >> 5)) * Np + nB + (l4 & 31) * 4);
            }
        }
        const unsigned* Wc = Ws + cur * WS_BUF;
        const unsigned* Xc = Xs + cur * XS_BUF;
        #pragma unroll
        for (int ks = 0; ks < 4; ks++) {
            const int kb = ks * 8;
            unsigned afr[4][4];
            #pragma unroll
            for (int mt = 0; mt < 4; mt++) {
                int row = wc + mt * 16 + gid;
                afr[mt][0] = Wc[row * WS_STRIDE + kb + tig];
                afr[mt][1] = Wc[(row + 8) * WS_STRIDE + kb + tig];
                afr[mt][2] = Wc[row * WS_STRIDE + kb + tig + 4];
                afr[mt][3] = Wc[(row + 8) * WS_STRIDE + kb + tig + 4];
            }
            unsigned bfr[4][2];
            #pragma unroll
            for (int nt = 0; nt < 4; nt++) {
                int col = wn + nt * 8 + gid;
                bfr[nt][0] = Xc[(kb + tig) * XS_STRIDE + col];
                bfr[nt][1] = Xc[(kb + tig + 4) * XS_STRIDE + col];
            }
            #pragma unroll
            for (int mt = 0; mt < 4; mt++)
                #pragma unroll
                for (int nt = 0; nt < 4; nt++)
                    mma_tf32(acc[mt][nt], afr[mt], bfr[nt]);
        }
        if (it + 1 < NI) {
            unsigned* Wd = Ws + (cur ^ 1) * WS_BUF;
            unsigned* Xd = Xs + (cur ^ 1) * XS_BUF;
            #pragma unroll
            for (int r = 0; r < 4; r++) {
                int l4 = t + 256 * r;
                unsigned* wd = Wd + (l4 >> 3) * WS_STRIDE + (l4 & 7) * 4;
                wd[0] = f2tf32(wst[r].x); wd[1] = f2tf32(wst[r].y);
                wd[2] = f2tf32(wst[r].z); wd[3] = f2tf32(wst[r].w);
                unsigned* xd = Xd + (l4 >> 5) * XS_STRIDE + (l4 & 31) * 4;
                xd[0] = f2tf32(xst[r].x); xd[1] = f2tf32(xst[r].y);
                xd[2] = f2tf32(xst[r].z); xd[3] = f2tf32(xst[r].w);
            }
            __syncthreads();
        }
    }

    // Epilogue: round to bf16, store V^T [c][m=n]
    __nv_bfloat16* Vb = vt + (size_t)b * Cch * Np;
    #pragma unroll
    for (int mt = 0; mt < 4; mt++) {
        int c = cB + wc + mt * 16 + gid;
        float b0 = bias[c], b1 = bias[c + 8];
        #pragma unroll
        for (int nt = 0; nt < 4; nt++) {
            int n = nB + wn + nt * 8 + 2 * tig;
            *(uint32_t*)(Vb + (size_t)c * Np + n) =
                pack2(__float2bfloat16_rn(acc[mt][nt][0] + b0),
                      __float2bfloat16_rn(acc[mt][nt][1] + b0));
            *(uint32_t*)(Vb + (size_t)(c + 8) * Np + n) =
                pack2(__float2bfloat16_rn(acc[mt][nt][2] + b1),
                      __float2bfloat16_rn(acc[mt][nt][3] + b1));
        }
    }
}

// ---------------------------------------------------------------------------
// sim via 3x bf16 split MMA (hh + hl + lh; ll term ~1.5e-4 abs, dropped),
// FUSED exp epilogue:
//   e[n][m] = exp(q.k - EXP_OFF)  -> bf16 P;  rowsum[n] += partial sums.
// Half the tensor instructions of the 3xTF32 version (k16 vs k8 steps).
// Smem rows: 16 payload words (32 bf16) padded to 20 -> conflict-free
// fragment banks (20*gid + tig pattern, proven in ctx kernel).
// ---------------------------------------------------------------------------
#define QB_STRIDE 20
#define QB_BUF (128 * QB_STRIDE)     // 2560 words = 10240 B per plane

__global__ __launch_bounds__(256) void sim_bf16_kernel(
        const float* __restrict__ q,
        const float* __restrict__ k,
        __nv_bfloat16* __restrict__ P,
        float* __restrict__ rowsum) {
    const int m0 = blockIdx.x * 128;
    const int n0 = blockIdx.y * 128;
    const int b  = blockIdx.z;

    __shared__ uint32_t qh[QB_BUF], ql[QB_BUF], kh[QB_BUF], kl[QB_BUF];

    const int t    = threadIdx.x;
    const int wid  = t >> 5;
    const int lane = t & 31;
    const int gid  = lane >> 2;
    const int tig  = lane & 3;
    const int wn   = (wid >> 2) * 64;
    const int wm   = (wid & 3) * 32;

    const float* qb = q + ((size_t)b * Np + n0) * Cqd;
    const float* kb = k + ((size_t)b * Np + m0) * Cqd;

    float acc[4][4][4] = {};

    for (int c0 = 0; c0 < Cqd; c0 += 32) {
        if (c0) __syncthreads();
        // Load + split one 128x32 chunk of q and k into bf16 hi/lo planes.
        #pragma unroll
        for (int r = 0; r < 4; r++) {
            int l4 = t + 256 * r;                 // 1024 float4 per operand
            int row = l4 >> 3, j4 = (l4 & 7) * 4; // k cols j4..j4+3
            float4 vq = *(const float4*)(qb + row * Cqd + c0 + j4);
            float4 vk = *(const float4*)(kb + row * Cqd + c0 + j4);
            __nv_bfloat16 hx, lx, hy, ly, hz, lz, hw, lw;
            int w0 = row * QB_STRIDE + (j4 >> 1);  // word holds k pair (j4, j4+1)
            split_bf16(vq.x, hx, lx); split_bf16(vq.y, hy, ly);
            split_bf16(vq.z, hz, lz); split_bf16(vq.w, hw, lw);
            qh[w0]     = pack2(hx, hy); qh[w0 + 1] = pack2(hz, hw);
            ql[w0]     = pack2(lx, ly); ql[w0 + 1] = pack2(lz, lw);
            split_bf16(vk.x, hx, lx); split_bf16(vk.y, hy, ly);
            split_bf16(vk.z, hz, lz); split_bf16(vk.w, hw, lw);
            kh[w0]     = pack2(hx, hy); kh[w0 + 1] = pack2(hz, hw);
            kl[w0]     = pack2(lx, ly); kl[w0 + 1] = pack2(lz, lw);
        }
        __syncthreads();

        #pragma unroll
        for (int ks = 0; ks < 2; ks++) {          // two k16 steps per 32-chunk
            const int kb8 = ks * 8;
            unsigned ah[4][4], al[4][4];
            #pragma unroll
            for (int mt = 0; mt < 4; mt++) {
                int row = wn + mt * 16 + gid;
                ah[mt][0] = qh[row * QB_STRIDE + kb8 + tig];
                ah[mt][1] = qh[(row + 8) * QB_STRIDE + kb8 + tig];
                ah[mt][2] = qh[row * QB_STRIDE + kb8 + tig + 4];
                ah[mt][3] = qh[(row + 8) * QB_STRIDE + kb8 + tig + 4];
                al[mt][0] = ql[row * QB_STRIDE + kb8 + tig];
                al[mt][1] = ql[(row + 8) * QB_STRIDE + kb8 + tig];
                al[mt][2] = ql[row * QB_STRIDE + kb8 + tig + 4];
                al[mt][3] = ql[(row + 8) * QB_STRIDE + kb8 + tig + 4];
            }
            unsigned bh[4][2], bl[4][2];
            #pragma unroll
            for (int nt = 0; nt < 4; nt++) {
                int col = wm + nt * 8 + gid;
                bh[nt][0] = kh[col * QB_STRIDE + kb8 + tig];
                bh[nt][1] = kh[col * QB_STRIDE + kb8 + tig + 4];
                bl[nt][0] = kl[col * QB_STRIDE + kb8 + tig];
                bl[nt][1] = kl[col * QB_STRIDE + kb8 + tig + 4];
            }
            #pragma unroll
            for (int mt = 0; mt < 4; mt++)
                #pragma unroll
                for (int nt = 0; nt < 4; nt++) {
                    mma_bf16(acc[mt][nt], ah[mt], bl[nt]);   // cross terms first
                    mma_bf16(acc[mt][nt], al[mt], bh[nt]);
                    mma_bf16(acc[mt][nt], ah[mt], bh[nt]);   // main term
                }
        }
    }

    // Fused exp epilogue
    #pragma unroll
    for (int mt = 0; mt < 4; mt++)
        #pragma unroll
        for (int nt = 0; nt < 4; nt++)
            #pragma unroll
            for (int v = 0; v < 4; v++)
                acc[mt][nt][v] = __expf(acc[mt][nt][v] - EXP_OFF);

    __nv_bfloat16* Pb = P + ((size_t)b * Np + n0) * Np + m0;
    #pragma unroll
    for (int mt = 0; mt < 4; mt++) {
        int n = wn + mt * 16 + gid;
        #pragma unroll
        for (int nt = 0; nt < 4; nt++) {
            int m = wm + nt * 8 + 2 * tig;
            *(uint32_t*)(Pb + (size_t)n * Np + m) =
                pack2(__float2bfloat16_rn(acc[mt][nt][0]),
                      __float2bfloat16_rn(acc[mt][nt][1]));
            *(uint32_t*)(Pb + (size_t)(n + 8) * Np + m) =
                pack2(__float2bfloat16_rn(acc[mt][nt][2]),
                      __float2bfloat16_rn(acc[mt][nt][3]));
        }
    }

    // Row partial sums: reduce over this thread's 8 m-values, then over the
    // quad (tig 0-3 share the same rows), then atomicAdd (spread addresses).
    float* rs = rowsum + (size_t)b * Np + n0;
    #pragma unroll
    for (int mt = 0; mt < 4; mt++) {
        float s0 = 0.f, s1 = 0.f;
        #pragma unroll
        for (int nt = 0; nt < 4; nt++) {
            s0 += acc[mt][nt][0] + acc[mt][nt][1];
            s1 += acc[mt][nt][2] + acc[mt][nt][3];
        }
        s0 += __shfl_xor_sync(0xFFFFFFFF, s0, 1);
        s0 += __shfl_xor_sync(0xFFFFFFFF, s0, 2);
        s1 += __shfl_xor_sync(0xFFFFFFFF, s1, 1);
        s1 += __shfl_xor_sync(0xFFFFFFFF, s1, 2);
        if (tig == 0) {
            int n = wn + mt * 16 + gid;
            atomicAdd(rs + n, s0);
            atomicAdd(rs + n + 8, s1);
        }
    }
}

// ---------------------------------------------------------------------------
// ctx via bf16 mma.sync m16n8k16; epilogue divides by rowsum:
//   out[b][c][n] = g * (sum_m e[n][m]*V[m][c]) / rowsum[n] + x
// ---------------------------------------------------------------------------
#define PS2 20
#define CT_BUF (128 * PS2)

__global__ __launch_bounds__(256) void ctx_bf16_kernel(
        const __nv_bfloat16* __restrict__ P,
        const __nv_bfloat16* __restrict__ Vt,
        const float* __restrict__ rowsum,
        const float* __restrict__ x,
        const float* __restrict__ gamma,
        float* __restrict__ out) {
    const int n0 = blockIdx.x * 128;
    const int c0 = blockIdx.y * 128;
    const int b  = blockIdx.z;

    __shared__ uint32_t Ps[2][CT_BUF];
    __shared__ uint32_t Vs[2][CT_BUF];

    const int t    = threadIdx.x;
    const int wid  = t >> 5;
    const int lane = t & 31;
    const int gid  = lane >> 2;
    const int tig  = lane & 3;
    const int wn   = (wid >> 2) * 64;
    const int wc   = (wid & 3) * 32;

    const __nv_bfloat16* Pb = P + ((size_t)b * Np + n0) * Np;
    const __nv_bfloat16* Vb = Vt + ((size_t)b * Cch + c0) * Np;

    float acc[4][4][4] = {};
    uint4 pst[2], vst[2];

    #pragma unroll
    for (int r = 0; r < 2; r++) {
        int l = t + 256 * r;
        int row = l >> 2, u = l & 3;
        pst[r] = *(const uint4*)(Pb + (size_t)row * Np + u * 8);
        vst[r] = *(const uint4*)(Vb + (size_t)row * Np + u * 8);
    }
    #pragma unroll
    for (int r = 0; r < 2; r++) {
        int l = t + 256 * r;
        int row = l >> 2, u = l & 3;
        uint32_t* pd = &Ps[0][row * PS2 + u * 4];
        pd[0] = pst[r].x; pd[1] = pst[r].y; pd[2] = pst[r].z; pd[3] = pst[r].w;
        uint32_t* vd = &Vs[0][row * PS2 + u * 4];
        vd[0] = vst[r].x; vd[1] = vst[r].y; vd[2] = vst[r].z; vd[3] = vst[r].w;
    }
    __syncthreads();

    const int NI = Np / 32;
    for (int it = 0; it < NI; it++) {
        const int cur = it & 1;
        if (it + 1 < NI) {
            const __nv_bfloat16* Pn = Pb + (it + 1) * 32;
            const __nv_bfloat16* Vn = Vb + (it + 1) * 32;
            #pragma unroll
            for (int r = 0; r < 2; r++) {
                int l = t + 256 * r;
                int row = l >> 2, u = l & 3;
                pst[r] = *(const uint4*)(Pn + (size_t)row * Np + u * 8);
                vst[r] = *(const uint4*)(Vn + (size_t)row * Np + u * 8);
            }
        }
        const uint32_t* Pc = Ps[cur];
        const uint32_t* Vc = Vs[cur];
        #pragma unroll
        for (int ks = 0; ks < 2; ks++) {
            const int kb = ks * 8;
            unsigned afr[4][4];
            #pragma unroll
            for (int mt = 0; mt < 4; mt++) {
                int row = wn + mt * 16 + gid;
                afr[mt][0] = Pc[row * PS2 + kb + tig];
                afr[mt][1] = Pc[(row + 8) * PS2 + kb + tig];
                afr[mt][2] = Pc[row * PS2 + kb + tig + 4];
                afr[mt][3] = Pc[(row + 8) * PS2 + kb + tig + 4];
            }
            unsigned bfr[4][2];
            #pragma unroll
            for (int nt = 0; nt < 4; nt++) {
                int col = wc + nt * 8 + gid;
                bfr[nt][0] = Vc[col * PS2 + kb + tig];
                bfr[nt][1] = Vc[col * PS2 + kb + tig + 4];
            }
            #pragma unroll
            for (int mt = 0; mt < 4; mt++)
                #pragma unroll
                for (int nt = 0; nt < 4; nt++)
                    mma_bf16(acc[mt][nt], afr[mt], bfr[nt]);
        }
        if (it + 1 < NI) {
            uint32_t* Pd = Ps[cur ^ 1];
            uint32_t* Vd = Vs[cur ^ 1];
            #pragma unroll
            for (int r = 0; r < 2; r++) {
                int l = t + 256 * r;
                int row = l >> 2, u = l & 3;
                uint32_t* pd = &Pd[row * PS2 + u * 4];
                pd[0] = pst[r].x; pd[1] = pst[r].y; pd[2] = pst[r].z; pd[3] = pst[r].w;
                uint32_t* vd = &Vd[row * PS2 + u * 4];
                vd[0] = vst[r].x; vd[1] = vst[r].y; vd[2] = vst[r].z; vd[3] = vst[r].w;
            }
            __syncthreads();
        }
    }

    // Epilogue: out[b][c][n] = g * acc / rowsum[n] + x
    const float g = gamma[0];
    const float* rs = rowsum + (size_t)b * Np + n0;
    #pragma unroll
    for (int mt = 0; mt < 4; mt++) {
        int n = n0 + wn + mt * 16 + gid;
        float inv0 = g / rs[wn + mt * 16 + gid];
        float inv1 = g / rs[wn + mt * 16 + gid + 8];
        #pragma unroll
        for (int nt = 0; nt < 4; nt++) {
            int c = c0 + wc + nt * 8 + 2 * tig;
            size_t i00 = ((size_t)b * Cch + c) * Np + n;
            size_t i01 = ((size_t)b * Cch + c + 1) * Np + n;
            out[i00]     = inv0 * acc[mt][nt][0] + x[i00];
            out[i01]     = inv0 * acc[mt][nt][1] + x[i01];
            out[i00 + 8] = inv1 * acc[mt][nt][2] + x[i00 + 8];
            out[i01 + 8] = inv1 * acc[mt][nt][3] + x[i01 + 8];
        }
    }
}

// ---------------------------------------------------------------------------
extern "C" void kernel_launch(void* const* d_in, const int* in_sizes, int n_in,
                              void* d_out, int out_size) {
    const float* x     = (const float*)d_in[0];
    const float* Wq    = (const float*)d_in[1];
    const float* bq    = (const float*)d_in[2];
    const float* Wk    = (const float*)d_in[3];
    const float* bk    = (const float*)d_in[4];
    const float* Wv    = (const float*)d_in[5];
    const float* bv    = (const float*)d_in[6];
    const float* gamma = (const float*)d_in[7];
    float* out = (float*)d_out;

    float *q, *k, *rsum;
    __nv_bfloat16 *pb, *vt;
    cudaGetSymbolAddress((void**)&q, g_q);
    cudaGetSymbolAddress((void**)&k, g_k);
    cudaGetSymbolAddress((void**)&rsum, g_rowsum);
    cudaGetSymbolAddress((void**)&pb, g_pb);
    cudaGetSymbolAddress((void**)&vt, g_vt);

    static int smem_set = 0;
    if (!smem_set) {
        cudaFuncSetAttribute(vproj_tc_kernel,
                             cudaFuncAttributeMaxDynamicSharedMemorySize, VP_SMEM);
        smem_set = 1;
    }

    dim3 thr(256);
    zero_rowsum_kernel<<<Bsz * Np / 256, thr>>>(rsum);
    proj_kernel<<<dim3(Np / 128, 1, Bsz), thr>>>(x, Wq, bq, q, Cqd);
    proj_kernel<<<dim3(Np / 128, 1, Bsz), thr>>>(x, Wk, bk, k, Cqd);
    vproj_tc_kernel<<<dim3(Np / 128, Cch / 128, Bsz), thr, VP_SMEM>>>(x, Wv, bv, vt);
    sim_bf16_kernel<<<dim3(Np / 128, Np / 128, Bsz), thr>>>(q, k, pb, rsum);
    ctx_bf16_kernel<<<dim3(Np / 128, Cch / 128, Bsz), thr>>>(pb, vt, rsum, x, gamma, out);
}